// round 8
// baseline (speedup 1.0000x reference)
#include <cuda_runtime.h>
#include <cstdint>

#define NNODES 32768
#define EB 8   // edges/nodes per warp batch

__device__ float g_u[NNODES * 64];   // g_a[n] + pos[n]·W1r
__device__ float g_v[NNODES * 64];   // pos[n]·W1r

__device__ __forceinline__ void atomicMaxF(float* addr, float v) {
    if (v >= 0.0f) atomicMax((int*)addr, __float_as_int(v));
    else           atomicMin((unsigned int*)addr, __float_as_uint(v));
}
__device__ __forceinline__ void unpack2(unsigned long long p, float& lo, float& hi) {
    asm("mov.b64 {%0,%1}, %2;" : "=f"(lo), "=f"(hi) : "l"(p));
}
__device__ __forceinline__ void fma2(unsigned long long& acc,
                                     unsigned long long a, unsigned long long b) {
    asm("fma.rn.f32x2 %0, %1, %2, %3;" : "=l"(acc) : "l"(a), "l"(b), "l"(acc));
}
__device__ __forceinline__ unsigned long long add2(unsigned long long a, unsigned long long b) {
    unsigned long long r;
    asm("add.rn.f32x2 %0, %1, %2;" : "=l"(r) : "l"(a), "l"(b));
    return r;
}

// W2 staged k-pair-major: w2a[q*32+j] = {W2[4q..4q+3][j]}, w2b same for j+32
__device__ __forceinline__ void stage_w2(const float* __restrict__ W2,
                                         float4* w2a, float4* w2b, int tid, int nthr) {
    for (int idx = tid; idx < 16 * 32; idx += nthr) {
        const int q = idx >> 5, j = idx & 31;
        const float* r0 = W2 + (4 * q) * 64;
        w2a[idx] = make_float4(r0[j],      r0[64 + j],      r0[128 + j],      r0[192 + j]);
        w2b[idx] = make_float4(r0[j + 32], r0[64 + j + 32], r0[128 + j + 32], r0[192 + j + 32]);
    }
}

// ---------------------------------------------------------------------------
// Kernel 1: per-node. t = x@W1[0:4]+b1 ; v = pos·W1r ; u = t+v.
// Stores u,v; initializes out with the self-loop value relu(t)@W2 + b2.
// ---------------------------------------------------------------------------
__global__ void __launch_bounds__(256, 2) node_kernel(
    const float* __restrict__ x, const float* __restrict__ pos,
    const float* __restrict__ W1, const float* __restrict__ b1,
    const float* __restrict__ W2, const float* __restrict__ b2,
    float* __restrict__ out)
{
    __shared__ float4 w2a[16 * 32];
    __shared__ float4 w2b[16 * 32];
    __shared__ __align__(16) float tds[8][EB * 64];

    const int tid = threadIdx.x, lane = tid & 31, w = tid >> 5;
    stage_w2(W2, w2a, w2b, tid, 256);
    __syncthreads();
    float* td = tds[w];

    float wxa[4], wxb[4];
#pragma unroll
    for (int i = 0; i < 4; i++) { wxa[i] = W1[i * 64 + lane]; wxb[i] = W1[i * 64 + lane + 32]; }
    const float wra0 = W1[4 * 64 + lane],      wra1 = W1[5 * 64 + lane],      wra2 = W1[6 * 64 + lane];
    const float wrb0 = W1[4 * 64 + lane + 32], wrb1 = W1[5 * 64 + lane + 32], wrb2 = W1[6 * 64 + lane + 32];
    const float b1a = b1[lane], b1b = b1[lane + 32];
    const float b2a = b2[lane], b2b = b2[lane + 32];

    const int gw = blockIdx.x * 8 + w, nW = gridDim.x * 8;
    const int perWarp = (NNODES + nW - 1) / nW;
    const int n0 = gw * perWarp;
    int n1 = n0 + perWarp; if (n1 > NNODES) n1 = NNODES;

    for (int base = n0; base < n1; base += EB) {
        const int nb = min(EB, n1 - base);
        __syncwarp();
#pragma unroll
        for (int i = 0; i < EB; i++) {
            if (i >= nb) break;
            const int n = base + i;
            const float x0 = x[n * 4 + 0], x1 = x[n * 4 + 1];
            const float x2 = x[n * 4 + 2], x3 = x[n * 4 + 3];
            float t0 = fmaf(x3, wxa[3], fmaf(x2, wxa[2], fmaf(x1, wxa[1], fmaf(x0, wxa[0], b1a))));
            float t1 = fmaf(x3, wxb[3], fmaf(x2, wxb[2], fmaf(x1, wxb[1], fmaf(x0, wxb[0], b1b))));
            const float p0 = pos[n * 3 + 0], p1 = pos[n * 3 + 1], p2 = pos[n * 3 + 2];
            const float v0 = fmaf(p2, wra2, fmaf(p1, wra1, p0 * wra0));
            const float v1 = fmaf(p2, wrb2, fmaf(p1, wrb1, p0 * wrb0));
            g_v[(size_t)n * 64 + lane]      = v0;
            g_v[(size_t)n * 64 + 32 + lane] = v1;
            g_u[(size_t)n * 64 + lane]      = t0 + v0;
            g_u[(size_t)n * 64 + 32 + lane] = t1 + v1;
            td[i * 64 + lane]      = fmaxf(t0, 0.0f);
            td[i * 64 + lane + 32] = fmaxf(t1, 0.0f);
        }
        __syncwarp();

        unsigned long long acc[EB][2];
#pragma unroll
        for (int i = 0; i < EB; i++) { acc[i][0] = 0ull; acc[i][1] = 0ull; }
#pragma unroll
        for (int q = 0; q < 16; q++) {
            const ulonglong2 wa = *reinterpret_cast<const ulonglong2*>(&w2a[q * 32 + lane]);
            const ulonglong2 wb = *reinterpret_cast<const ulonglong2*>(&w2b[q * 32 + lane]);
#pragma unroll
            for (int i = 0; i < EB; i++) {
                const ulonglong2 tq = *reinterpret_cast<const ulonglong2*>(&td[i * 64 + q * 4]);
                fma2(acc[i][0], tq.x, wa.x);
                fma2(acc[i][0], tq.y, wa.y);
                fma2(acc[i][1], tq.x, wb.x);
                fma2(acc[i][1], tq.y, wb.y);
            }
        }
#pragma unroll
        for (int i = 0; i < EB; i++) {
            if (i >= nb) break;
            float a, b, c, d;
            unpack2(acc[i][0], a, b);
            unpack2(acc[i][1], c, d);
            const int n = base + i;
            out[(size_t)n * 64 + lane]      = a + b + b2a;
            out[(size_t)n * 64 + 32 + lane] = c + d + b2b;
        }
    }
}

// ---------------------------------------------------------------------------
// Kernel 2: per-edge. t = relu(u[src] - v[dst]) with segment-cached v[dst],
// ei prefetch, two-pass gemm with split (even/odd q) accumulator chains.
// ---------------------------------------------------------------------------
__global__ void __launch_bounds__(128, 5) edge_kernel(
    const int* __restrict__ ei, long long E,
    const float* __restrict__ W2, const float* __restrict__ b2,
    float* __restrict__ out)
{
    extern __shared__ char smem[];
    float4* w2a = (float4*)smem;               // 8 KB
    float4* w2b = (float4*)(smem + 8192);      // 8 KB
    float*  tds = (float*)(smem + 16384);      // 8 KB: [4][512]

    const int tid = threadIdx.x, lane = tid & 31, w = tid >> 5;
    stage_w2(W2, w2a, w2b, tid, 128);
    __syncthreads();

    float* tb = tds + w * 512;

    const float b2a = b2[lane], b2b = b2[lane + 32];
    const int* __restrict__ srcA = ei;
    const int* __restrict__ dstA = ei + E;

    const long long gw = blockIdx.x * 4 + w;
    const long long nW = (long long)gridDim.x * 4;
    long long chunk = (E + nW - 1) / nW;
    chunk = (chunk + EB - 1) / EB * EB;        // EB-aligned chunks
    const long long e0 = gw * chunk;
    long long e1 = e0 + chunk; if (e1 > E) e1 = E;
    if (e0 >= e1) return;

    auto loadEI = [&](long long base, int* s, int* d) {
        if (base + EB <= E) {
            const int4 s0 = *reinterpret_cast<const int4*>(srcA + base);
            const int4 s1 = *reinterpret_cast<const int4*>(srcA + base + 4);
            const int4 d0 = *reinterpret_cast<const int4*>(dstA + base);
            const int4 d1 = *reinterpret_cast<const int4*>(dstA + base + 4);
            s[0] = s0.x; s[1] = s0.y; s[2] = s0.z; s[3] = s0.w;
            s[4] = s1.x; s[5] = s1.y; s[6] = s1.z; s[7] = s1.w;
            d[0] = d0.x; d[1] = d0.y; d[2] = d0.z; d[3] = d0.w;
            d[4] = d1.x; d[5] = d1.y; d[6] = d1.z; d[7] = d1.w;
        } else {
#pragma unroll
            for (int i = 0; i < EB; i++) {
                const long long e = base + i;
                s[i] = (e < E) ? srcA[e] : 0;
                d[i] = (e < E) ? dstA[e] : 0;
            }
        }
    };

    int ssC[EB], ddC[EB], ssN[EB], ddN[EB];
    loadEI(e0, ssC, ddC);

    int cur = -1;
    float m0 = -3.4e38f, m1 = -3.4e38f;
    int dprev = -1;
    float vc0 = 0.0f, vc1 = 0.0f;

    for (long long base = e0; base < e1; base += EB) {
        const int nb = (int)min((long long)EB, e1 - base);
        const long long nxt = base + EB;

        bool anyreal = false;
#pragma unroll
        for (int i = 0; i < EB; i++)
            if (i < nb && ssC[i] != ddC[i]) anyreal = true;
        if (!anyreal) {                         // pure self-loop/pad batch
            if (nxt < e1) loadEI(nxt, ssC, ddC);
            continue;
        }

        __syncwarp();
#pragma unroll
        for (int i = 0; i < EB; i++) {
            const int s = ssC[i], d = (i < nb) ? ddC[i] : ddC[0];
            if (d != dprev) {                   // uniform across warp
                vc0 = g_v[(size_t)d * 64 + lane];
                vc1 = g_v[(size_t)d * 64 + 32 + lane];
                dprev = d;
            }
            const float uu0 = g_u[(size_t)s * 64 + lane];
            const float uu1 = g_u[(size_t)s * 64 + 32 + lane];
            tb[i * 64 + lane]      = fmaxf(uu0 - vc0, 0.0f);
            tb[i * 64 + 32 + lane] = fmaxf(uu1 - vc1, 0.0f);
        }
        __syncwarp();

        if (nxt < e1) loadEI(nxt, ssN, ddN);    // prefetch under the gemm

#pragma unroll
        for (int half = 0; half < 2; half++) {
            // 4 edges x 2 channels x (even/odd q) = 16 independent chains
            unsigned long long acc[4][4];
#pragma unroll
            for (int i = 0; i < 4; i++)
#pragma unroll
                for (int j = 0; j < 4; j++) acc[i][j] = 0ull;

#pragma unroll
            for (int q = 0; q < 16; q += 2) {
                const ulonglong2 wa0 = *reinterpret_cast<const ulonglong2*>(&w2a[q * 32 + lane]);
                const ulonglong2 wb0 = *reinterpret_cast<const ulonglong2*>(&w2b[q * 32 + lane]);
                const ulonglong2 wa1 = *reinterpret_cast<const ulonglong2*>(&w2a[(q + 1) * 32 + lane]);
                const ulonglong2 wb1 = *reinterpret_cast<const ulonglong2*>(&w2b[(q + 1) * 32 + lane]);
#pragma unroll
                for (int i = 0; i < 4; i++) {
                    const float* te = &tb[(half * 4 + i) * 64];
                    const ulonglong2 t0 = *reinterpret_cast<const ulonglong2*>(te + q * 4);
                    const ulonglong2 t1 = *reinterpret_cast<const ulonglong2*>(te + q * 4 + 4);
                    fma2(acc[i][0], t0.x, wa0.x);
                    fma2(acc[i][1], t0.y, wa0.y);
                    fma2(acc[i][2], t0.x, wb0.x);
                    fma2(acc[i][3], t0.y, wb0.y);
                    fma2(acc[i][0], t1.x, wa1.x);
                    fma2(acc[i][1], t1.y, wa1.y);
                    fma2(acc[i][2], t1.x, wb1.x);
                    fma2(acc[i][3], t1.y, wb1.y);
                }
            }

#pragma unroll
            for (int i = 0; i < 4; i++) {
                const int e = half * 4 + i;
                if (e >= nb) break;
                if (ssC[e] == ddC[e]) continue;     // self-loop/pad: covered by init
                const unsigned long long fa = add2(acc[i][0], acc[i][1]);
                const unsigned long long fb = add2(acc[i][2], acc[i][3]);
                float a, b, c, d2;
                unpack2(fa, a, b);
                unpack2(fb, c, d2);
                const float h0 = a + b + b2a;
                const float h1 = c + d2 + b2b;
                const int d = ddC[e];
                if (d != cur) {
                    if (cur >= 0) {
                        atomicMaxF(&out[(size_t)cur * 64 + lane],      m0);
                        atomicMaxF(&out[(size_t)cur * 64 + 32 + lane], m1);
                    }
                    cur = d;
                    m0 = -3.4e38f; m1 = -3.4e38f;
                }
                m0 = fmaxf(m0, h0);
                m1 = fmaxf(m1, h1);
            }
        }

        if (nxt < e1) {
#pragma unroll
            for (int i = 0; i < EB; i++) { ssC[i] = ssN[i]; ddC[i] = ddN[i]; }
        }
    }
    if (cur >= 0) {
        atomicMaxF(&out[(size_t)cur * 64 + lane],      m0);
        atomicMaxF(&out[(size_t)cur * 64 + 32 + lane], m1);
    }
}

// ---------------------------------------------------------------------------
// Kernel 3: pos + batch (as float) tail of the flattened tuple output.
// ---------------------------------------------------------------------------
__global__ void tail_kernel(const float* __restrict__ pos,
                            const int* __restrict__ batch,
                            float* __restrict__ out, int tail)
{
    int i = blockIdx.x * blockDim.x + threadIdx.x;
    if (i >= tail) return;
    float v;
    if (i < NNODES * 3) v = pos[i];
    else {
        int k = i - NNODES * 3;
        v = (k < NNODES) ? (float)batch[k] : 0.0f;
    }
    out[NNODES * 64 + i] = v;
}

extern "C" void kernel_launch(void* const* d_in, const int* in_sizes, int n_in,
                              void* d_out, int out_size) {
    const float* x     = (const float*)d_in[0];
    const float* pos   = (const float*)d_in[1];
    const int*   batch = (const int*)d_in[2];
    const int*   ei    = (const int*)d_in[3];
    const float* W1    = (const float*)d_in[4];
    const float* b1    = (const float*)d_in[5];
    const float* W2    = (const float*)d_in[6];
    const float* b2    = (const float*)d_in[7];
    float* out = (float*)d_out;

    const long long E = (long long)in_sizes[3] / 2;

    cudaFuncSetAttribute(edge_kernel, cudaFuncAttributeMaxDynamicSharedMemorySize, 24576);

    node_kernel<<<296, 256>>>(x, pos, W1, b1, W2, b2, out);
    edge_kernel<<<740, 128, 24576>>>(ei, E, W2, b2, out);

    int tail = out_size - NNODES * 64;
    if (tail > 0) tail_kernel<<<(tail + 255) / 256, 256>>>(pos, batch, out, tail);
}

// round 9
// speedup vs baseline: 1.7955x; 1.7955x over previous
#include <cuda_runtime.h>
#include <cstdint>

#define NNODES 32768
#define EB 8     // node-kernel batch
#define ET 16    // edge-kernel tile (two 8-edge gemm passes)

__device__ float g_u[NNODES * 64];   // g_a[n] + pos[n]·W1r
__device__ float g_v[NNODES * 64];   // pos[n]·W1r

__device__ __forceinline__ void atomicMaxF(float* addr, float v) {
    if (v >= 0.0f) atomicMax((int*)addr, __float_as_int(v));
    else           atomicMin((unsigned int*)addr, __float_as_uint(v));
}
__device__ __forceinline__ void unpack2(unsigned long long p, float& lo, float& hi) {
    asm("mov.b64 {%0,%1}, %2;" : "=f"(lo), "=f"(hi) : "l"(p));
}
__device__ __forceinline__ void fma2(unsigned long long& acc,
                                     unsigned long long a, unsigned long long b) {
    asm("fma.rn.f32x2 %0, %1, %2, %3;" : "=l"(acc) : "l"(a), "l"(b), "l"(acc));
}

// W2 staged k-pair-major: w2a[q*32+j] = {W2[4q..4q+3][j]}, w2b same for j+32
__device__ __forceinline__ void stage_w2(const float* __restrict__ W2,
                                         float4* w2a, float4* w2b, int tid, int nthr) {
    for (int idx = tid; idx < 16 * 32; idx += nthr) {
        const int q = idx >> 5, j = idx & 31;
        const float* r0 = W2 + (4 * q) * 64;
        w2a[idx] = make_float4(r0[j],      r0[64 + j],      r0[128 + j],      r0[192 + j]);
        w2b[idx] = make_float4(r0[j + 32], r0[64 + j + 32], r0[128 + j + 32], r0[192 + j + 32]);
    }
}

// ---------------------------------------------------------------------------
// Kernel 1: per-node. t = x@W1[0:4]+b1 ; v = pos·W1r ; u = t+v.
// Stores u,v; initializes out with the self-loop value relu(t)@W2 + b2.
// ---------------------------------------------------------------------------
__global__ void __launch_bounds__(256, 2) node_kernel(
    const float* __restrict__ x, const float* __restrict__ pos,
    const float* __restrict__ W1, const float* __restrict__ b1,
    const float* __restrict__ W2, const float* __restrict__ b2,
    float* __restrict__ out)
{
    __shared__ float4 w2a[16 * 32];
    __shared__ float4 w2b[16 * 32];
    __shared__ __align__(16) float tds[8][EB * 64];

    const int tid = threadIdx.x, lane = tid & 31, w = tid >> 5;
    stage_w2(W2, w2a, w2b, tid, 256);
    __syncthreads();
    float* td = tds[w];

    float wxa[4], wxb[4];
#pragma unroll
    for (int i = 0; i < 4; i++) { wxa[i] = W1[i * 64 + lane]; wxb[i] = W1[i * 64 + lane + 32]; }
    const float wra0 = W1[4 * 64 + lane],      wra1 = W1[5 * 64 + lane],      wra2 = W1[6 * 64 + lane];
    const float wrb0 = W1[4 * 64 + lane + 32], wrb1 = W1[5 * 64 + lane + 32], wrb2 = W1[6 * 64 + lane + 32];
    const float b1a = b1[lane], b1b = b1[lane + 32];
    const float b2a = b2[lane], b2b = b2[lane + 32];

    const int gw = blockIdx.x * 8 + w, nW = gridDim.x * 8;
    const int perWarp = (NNODES + nW - 1) / nW;
    const int n0 = gw * perWarp;
    int n1 = n0 + perWarp; if (n1 > NNODES) n1 = NNODES;

    for (int base = n0; base < n1; base += EB) {
        const int nb = min(EB, n1 - base);
        __syncwarp();
#pragma unroll
        for (int i = 0; i < EB; i++) {
            if (i >= nb) break;
            const int n = base + i;
            const float x0 = x[n * 4 + 0], x1 = x[n * 4 + 1];
            const float x2 = x[n * 4 + 2], x3 = x[n * 4 + 3];
            float t0 = fmaf(x3, wxa[3], fmaf(x2, wxa[2], fmaf(x1, wxa[1], fmaf(x0, wxa[0], b1a))));
            float t1 = fmaf(x3, wxb[3], fmaf(x2, wxb[2], fmaf(x1, wxb[1], fmaf(x0, wxb[0], b1b))));
            const float p0 = pos[n * 3 + 0], p1 = pos[n * 3 + 1], p2 = pos[n * 3 + 2];
            const float v0 = fmaf(p2, wra2, fmaf(p1, wra1, p0 * wra0));
            const float v1 = fmaf(p2, wrb2, fmaf(p1, wrb1, p0 * wrb0));
            g_v[(size_t)n * 64 + lane]      = v0;
            g_v[(size_t)n * 64 + 32 + lane] = v1;
            g_u[(size_t)n * 64 + lane]      = t0 + v0;
            g_u[(size_t)n * 64 + 32 + lane] = t1 + v1;
            td[i * 64 + lane]      = fmaxf(t0, 0.0f);
            td[i * 64 + lane + 32] = fmaxf(t1, 0.0f);
        }
        __syncwarp();

        unsigned long long acc[EB][2];
#pragma unroll
        for (int i = 0; i < EB; i++) { acc[i][0] = 0ull; acc[i][1] = 0ull; }
#pragma unroll
        for (int q = 0; q < 16; q++) {
            const ulonglong2 wa = *reinterpret_cast<const ulonglong2*>(&w2a[q * 32 + lane]);
            const ulonglong2 wb = *reinterpret_cast<const ulonglong2*>(&w2b[q * 32 + lane]);
#pragma unroll
            for (int i = 0; i < EB; i++) {
                const ulonglong2 tq = *reinterpret_cast<const ulonglong2*>(&td[i * 64 + q * 4]);
                fma2(acc[i][0], tq.x, wa.x);
                fma2(acc[i][0], tq.y, wa.y);
                fma2(acc[i][1], tq.x, wb.x);
                fma2(acc[i][1], tq.y, wb.y);
            }
        }
#pragma unroll
        for (int i = 0; i < EB; i++) {
            if (i >= nb) break;
            float a, b, c, d;
            unpack2(acc[i][0], a, b);
            unpack2(acc[i][1], c, d);
            const int n = base + i;
            out[(size_t)n * 64 + lane]      = a + b + b2a;
            out[(size_t)n * 64 + 32 + lane] = c + d + b2b;
        }
    }
}

// ---------------------------------------------------------------------------
// Kernel 2: per-edge. 16-edge tiles: one ei load / v-cache build / syncwarp
// pair, then TWO 8-edge gemm passes reusing acc[8][2] (w2 LSU halved/edge).
// ---------------------------------------------------------------------------
__global__ void __launch_bounds__(128, 4) edge_kernel(
    const int* __restrict__ ei, long long E,
    const float* __restrict__ W2, const float* __restrict__ b2,
    float* __restrict__ out)
{
    extern __shared__ char smem[];
    float4* w2a = (float4*)smem;               //  8 KB
    float4* w2b = (float4*)(smem + 8192);      //  8 KB
    float*  tds = (float*)(smem + 16384);      // 16 KB: [4][ET*64]

    const int tid = threadIdx.x, lane = tid & 31, w = tid >> 5;
    stage_w2(W2, w2a, w2b, tid, 128);
    __syncthreads();

    float* tb = tds + w * (ET * 64);

    const float b2a = b2[lane], b2b = b2[lane + 32];
    const int* __restrict__ srcA = ei;
    const int* __restrict__ dstA = ei + E;

    const long long gw = blockIdx.x * 4 + w;
    const long long nW = (long long)gridDim.x * 4;
    long long chunk = (E + nW - 1) / nW;
    chunk = (chunk + ET - 1) / ET * ET;        // ET-aligned chunks
    const long long e0 = gw * chunk;
    long long e1 = e0 + chunk; if (e1 > E) e1 = E;
    if (e0 >= e1) return;

    int cur = -1;
    float m0 = -3.4e38f, m1 = -3.4e38f;
    int dprev = -1;
    float vc0 = 0.0f, vc1 = 0.0f;

    for (long long base = e0; base < e1; base += ET) {
        const int nb = (int)min((long long)ET, e1 - base);
        int ss[ET], dd[ET];

        if (base + ET <= E) {
#pragma unroll
            for (int p = 0; p < ET / 4; p++) {
                const int4 sv = *reinterpret_cast<const int4*>(srcA + base + 4 * p);
                const int4 dv = *reinterpret_cast<const int4*>(dstA + base + 4 * p);
                ss[4 * p + 0] = sv.x; ss[4 * p + 1] = sv.y; ss[4 * p + 2] = sv.z; ss[4 * p + 3] = sv.w;
                dd[4 * p + 0] = dv.x; dd[4 * p + 1] = dv.y; dd[4 * p + 2] = dv.z; dd[4 * p + 3] = dv.w;
            }
        } else {
#pragma unroll
            for (int i = 0; i < ET; i++) {
                const long long e = base + i;
                ss[i] = (e < E) ? srcA[e] : 0;
                dd[i] = (e < E) ? dstA[e] : 0;
            }
        }

        bool anyreal = false;
#pragma unroll
        for (int i = 0; i < ET; i++)
            if (i < nb && ss[i] != dd[i]) anyreal = true;
        if (!anyreal) continue;                 // pure self-loop/pad tile

        __syncwarp();
#pragma unroll
        for (int i = 0; i < ET; i++) {
            const int s = ss[i], d = (i < nb) ? dd[i] : dd[0];
            if (d != dprev) {                   // uniform across warp
                vc0 = g_v[(size_t)d * 64 + lane];
                vc1 = g_v[(size_t)d * 64 + 32 + lane];
                dprev = d;
            }
            const float uu0 = g_u[(size_t)s * 64 + lane];
            const float uu1 = g_u[(size_t)s * 64 + 32 + lane];
            tb[i * 64 + lane]      = fmaxf(uu0 - vc0, 0.0f);
            tb[i * 64 + 32 + lane] = fmaxf(uu1 - vc1, 0.0f);
        }
        __syncwarp();

#pragma unroll
        for (int half = 0; half < 2; half++) {
            const float* th = tb + half * 8 * 64;

            unsigned long long acc[8][2];
#pragma unroll
            for (int i = 0; i < 8; i++) { acc[i][0] = 0ull; acc[i][1] = 0ull; }
#pragma unroll
            for (int q = 0; q < 16; q++) {
                const ulonglong2 wa = *reinterpret_cast<const ulonglong2*>(&w2a[q * 32 + lane]);
                const ulonglong2 wb = *reinterpret_cast<const ulonglong2*>(&w2b[q * 32 + lane]);
#pragma unroll
                for (int i = 0; i < 8; i++) {
                    const ulonglong2 tq = *reinterpret_cast<const ulonglong2*>(&th[i * 64 + q * 4]);
                    fma2(acc[i][0], tq.x, wa.x);
                    fma2(acc[i][0], tq.y, wa.y);
                    fma2(acc[i][1], tq.x, wb.x);
                    fma2(acc[i][1], tq.y, wb.y);
                }
            }

#pragma unroll
            for (int i = 0; i < 8; i++) {
                const int e = half * 8 + i;
                if (e >= nb) break;
                if (ss[e] == dd[e]) continue;   // self-loop/pad: covered by node init
                float a, b, c, d2;
                unpack2(acc[i][0], a, b);
                unpack2(acc[i][1], c, d2);
                const float h0 = a + b + b2a;
                const float h1 = c + d2 + b2b;
                const int d = dd[e];
                if (d != cur) {
                    if (cur >= 0) {
                        atomicMaxF(&out[(size_t)cur * 64 + lane],      m0);
                        atomicMaxF(&out[(size_t)cur * 64 + 32 + lane], m1);
                    }
                    cur = d;
                    m0 = -3.4e38f; m1 = -3.4e38f;
                }
                m0 = fmaxf(m0, h0);
                m1 = fmaxf(m1, h1);
            }
        }
    }
    if (cur >= 0) {
        atomicMaxF(&out[(size_t)cur * 64 + lane],      m0);
        atomicMaxF(&out[(size_t)cur * 64 + 32 + lane], m1);
    }
}

// ---------------------------------------------------------------------------
// Kernel 3: pos + batch (as float) tail of the flattened tuple output.
// ---------------------------------------------------------------------------
__global__ void tail_kernel(const float* __restrict__ pos,
                            const int* __restrict__ batch,
                            float* __restrict__ out, int tail)
{
    int i = blockIdx.x * blockDim.x + threadIdx.x;
    if (i >= tail) return;
    float v;
    if (i < NNODES * 3) v = pos[i];
    else {
        int k = i - NNODES * 3;
        v = (k < NNODES) ? (float)batch[k] : 0.0f;
    }
    out[NNODES * 64 + i] = v;
}

extern "C" void kernel_launch(void* const* d_in, const int* in_sizes, int n_in,
                              void* d_out, int out_size) {
    const float* x     = (const float*)d_in[0];
    const float* pos   = (const float*)d_in[1];
    const int*   batch = (const int*)d_in[2];
    const int*   ei    = (const int*)d_in[3];
    const float* W1    = (const float*)d_in[4];
    const float* b1    = (const float*)d_in[5];
    const float* W2    = (const float*)d_in[6];
    const float* b2    = (const float*)d_in[7];
    float* out = (float*)d_out;

    const long long E = (long long)in_sizes[3] / 2;

    cudaFuncSetAttribute(edge_kernel, cudaFuncAttributeMaxDynamicSharedMemorySize, 32768);

    node_kernel<<<296, 256>>>(x, pos, W1, b1, W2, b2, out);
    edge_kernel<<<592, 128, 32768>>>(ei, E, W2, b2, out);

    int tail = out_size - NNODES * 64;
    if (tail > 0) tail_kernel<<<(tail + 255) / 256, 256>>>(pos, batch, out, tail);
}

// round 10
// speedup vs baseline: 3.6780x; 2.0484x over previous
#include <cuda_runtime.h>
#include <cstdint>

#define NNODES 32768
#define EB 8     // node-kernel batch
#define ET 16    // edge-kernel tile (8 fma2-packed edge pairs, ONE gemm pass)

__device__ float g_u[NNODES * 64];   // g_a[n] + pos[n]·W1r
__device__ float g_v[NNODES * 64];   // pos[n]·W1r

__device__ __forceinline__ void atomicMaxF(float* addr, float v) {
    if (v >= 0.0f) atomicMax((int*)addr, __float_as_int(v));
    else           atomicMin((unsigned int*)addr, __float_as_uint(v));
}
__device__ __forceinline__ unsigned long long pack2(float lo, float hi) {
    unsigned long long r;
    asm("mov.b64 %0, {%1,%2};" : "=l"(r) : "f"(lo), "f"(hi));
    return r;
}
__device__ __forceinline__ void unpack2(unsigned long long p, float& lo, float& hi) {
    asm("mov.b64 {%0,%1}, %2;" : "=f"(lo), "=f"(hi) : "l"(p));
}
__device__ __forceinline__ void fma2(unsigned long long& acc,
                                     unsigned long long a, unsigned long long b) {
    asm("fma.rn.f32x2 %0, %1, %2, %3;" : "=l"(acc) : "l"(a), "l"(b), "l"(acc));
}

// W2 staged k-pair-major: w2a[q*32+j] = {W2[4q..4q+3][j]}, w2b same for j+32
__device__ __forceinline__ void stage_w2(const float* __restrict__ W2,
                                         float4* w2a, float4* w2b, int tid, int nthr) {
    for (int idx = tid; idx < 16 * 32; idx += nthr) {
        const int q = idx >> 5, j = idx & 31;
        const float* r0 = W2 + (4 * q) * 64;
        w2a[idx] = make_float4(r0[j],      r0[64 + j],      r0[128 + j],      r0[192 + j]);
        w2b[idx] = make_float4(r0[j + 32], r0[64 + j + 32], r0[128 + j + 32], r0[192 + j + 32]);
    }
}

// ---------------------------------------------------------------------------
// Kernel 1: per-node (unchanged from the 284.8us best). t = x@W1[0:4]+b1 ;
// v = pos·W1r ; u = t+v. Stores u,v; inits out with relu(t)@W2+b2.
// ---------------------------------------------------------------------------
__global__ void __launch_bounds__(256, 2) node_kernel(
    const float* __restrict__ x, const float* __restrict__ pos,
    const float* __restrict__ W1, const float* __restrict__ b1,
    const float* __restrict__ W2, const float* __restrict__ b2,
    float* __restrict__ out)
{
    __shared__ float4 w2a[16 * 32];
    __shared__ float4 w2b[16 * 32];
    __shared__ __align__(16) float tds[8][EB * 64];

    const int tid = threadIdx.x, lane = tid & 31, w = tid >> 5;
    stage_w2(W2, w2a, w2b, tid, 256);
    __syncthreads();
    float* td = tds[w];

    float wxa[4], wxb[4];
#pragma unroll
    for (int i = 0; i < 4; i++) { wxa[i] = W1[i * 64 + lane]; wxb[i] = W1[i * 64 + lane + 32]; }
    const float wra0 = W1[4 * 64 + lane],      wra1 = W1[5 * 64 + lane],      wra2 = W1[6 * 64 + lane];
    const float wrb0 = W1[4 * 64 + lane + 32], wrb1 = W1[5 * 64 + lane + 32], wrb2 = W1[6 * 64 + lane + 32];
    const float b1a = b1[lane], b1b = b1[lane + 32];
    const float b2a = b2[lane], b2b = b2[lane + 32];

    const int gw = blockIdx.x * 8 + w, nW = gridDim.x * 8;
    const int perWarp = (NNODES + nW - 1) / nW;
    const int n0 = gw * perWarp;
    int n1 = n0 + perWarp; if (n1 > NNODES) n1 = NNODES;

    for (int base = n0; base < n1; base += EB) {
        const int nb = min(EB, n1 - base);
        __syncwarp();
#pragma unroll
        for (int i = 0; i < EB; i++) {
            if (i >= nb) break;
            const int n = base + i;
            const float x0 = x[n * 4 + 0], x1 = x[n * 4 + 1];
            const float x2 = x[n * 4 + 2], x3 = x[n * 4 + 3];
            float t0 = fmaf(x3, wxa[3], fmaf(x2, wxa[2], fmaf(x1, wxa[1], fmaf(x0, wxa[0], b1a))));
            float t1 = fmaf(x3, wxb[3], fmaf(x2, wxb[2], fmaf(x1, wxb[1], fmaf(x0, wxb[0], b1b))));
            const float p0 = pos[n * 3 + 0], p1 = pos[n * 3 + 1], p2 = pos[n * 3 + 2];
            const float v0 = fmaf(p2, wra2, fmaf(p1, wra1, p0 * wra0));
            const float v1 = fmaf(p2, wrb2, fmaf(p1, wrb1, p0 * wrb0));
            g_v[(size_t)n * 64 + lane]      = v0;
            g_v[(size_t)n * 64 + 32 + lane] = v1;
            g_u[(size_t)n * 64 + lane]      = t0 + v0;
            g_u[(size_t)n * 64 + 32 + lane] = t1 + v1;
            td[i * 64 + lane]      = fmaxf(t0, 0.0f);
            td[i * 64 + lane + 32] = fmaxf(t1, 0.0f);
        }
        __syncwarp();

        unsigned long long acc[EB][2];
#pragma unroll
        for (int i = 0; i < EB; i++) { acc[i][0] = 0ull; acc[i][1] = 0ull; }
#pragma unroll
        for (int q = 0; q < 16; q++) {
            const ulonglong2 wa = *reinterpret_cast<const ulonglong2*>(&w2a[q * 32 + lane]);
            const ulonglong2 wb = *reinterpret_cast<const ulonglong2*>(&w2b[q * 32 + lane]);
#pragma unroll
            for (int i = 0; i < EB; i++) {
                const ulonglong2 tq = *reinterpret_cast<const ulonglong2*>(&td[i * 64 + q * 4]);
                fma2(acc[i][0], tq.x, wa.x);
                fma2(acc[i][0], tq.y, wa.y);
                fma2(acc[i][1], tq.x, wb.x);
                fma2(acc[i][1], tq.y, wb.y);
            }
        }
#pragma unroll
        for (int i = 0; i < EB; i++) {
            if (i >= nb) break;
            float a, b, c, d;
            unpack2(acc[i][0], a, b);
            unpack2(acc[i][1], c, d);
            const int n = base + i;
            out[(size_t)n * 64 + lane]      = a + b + b2a;
            out[(size_t)n * 64 + 32 + lane] = c + d + b2b;
        }
    }
}

// ---------------------------------------------------------------------------
// Kernel 2: per-edge, 16 edges per tile in ONE gemm pass via fma2 edge-pair
// packing (acc u64 = (h_even, h_odd)). Indices live in smem scratch (no
// per-thread arrays); validity in a ballot mask. W2 read once per 16 edges.
// ---------------------------------------------------------------------------
__global__ void __launch_bounds__(128, 5) edge_kernel(
    const int* __restrict__ ei, long long E,
    const float* __restrict__ W2, const float* __restrict__ b2,
    float* __restrict__ out)
{
    extern __shared__ char smem[];
    float4* w2a  = (float4*)smem;                 //  8 KB
    float4* w2b  = (float4*)(smem + 8192);        //  8 KB
    float*  tds  = (float*)(smem + 16384);        // 16 KB: 4 warps x 8 pairs x 128
    int2*   sidx = (int2*)(smem + 32768);         // 512 B: 4 warps x 16

    const int tid = threadIdx.x, lane = tid & 31, w = tid >> 5;
    const unsigned FULL = 0xffffffffu;
    stage_w2(W2, w2a, w2b, tid, 128);
    __syncthreads();

    float* tb = tds + w * 1024;
    int2*  six = sidx + w * 16;

    const float b2a = b2[lane], b2b = b2[lane + 32];
    const int* __restrict__ srcA = ei;
    const int* __restrict__ dstA = ei + E;

    const long long gw = blockIdx.x * 4 + w;
    const long long nW = (long long)gridDim.x * 4;
    long long chunk = (E + nW - 1) / nW;
    chunk = (chunk + ET - 1) / ET * ET;
    const long long e0 = gw * chunk;
    long long e1 = e0 + chunk; if (e1 > E) e1 = E;
    if (e0 >= e1) return;

    int cur = -1;
    float m0 = -3.4e38f, m1 = -3.4e38f;
    int dprev = -1;
    float vc0 = 0.0f, vc1 = 0.0f;

    for (long long base = e0; base < e1; base += ET) {
        __syncwarp();   // protect six / tb reuse across iterations

        // ---- index load: lanes 0-15, coalesced; invalid/self edges -> (0,0) ----
        int sL = 0, dL = 0;
        if (lane < ET) {
            const long long e = base + lane;
            if (e < e1) { sL = srcA[e]; dL = dstA[e]; }
            six[lane] = make_int2(sL, dL);
        }
        const unsigned mask = __ballot_sync(FULL, (lane < ET) && (sL != dL));
        if (!mask) continue;                    // pure self-loop/pad tile
        __syncwarp();

        // ---- t-phase: t = relu(u[s] - v[d]), v segment-cached; pair-interleaved ----
#pragma unroll
        for (int i = 0; i < ET; i++) {
            const int2 sd = six[i];             // broadcast LDS
            if (sd.y != dprev) {                // warp-uniform
                vc0 = g_v[(size_t)sd.y * 64 + lane];
                vc1 = g_v[(size_t)sd.y * 64 + 32 + lane];
                dprev = sd.y;
            }
            const float uu0 = g_u[(size_t)sd.x * 64 + lane];
            const float uu1 = g_u[(size_t)sd.x * 64 + 32 + lane];
            const int p = i >> 1, par = i & 1;
            tb[p * 128 + lane * 2 + par]        = fmaxf(uu0 - vc0, 0.0f);
            tb[p * 128 + (lane + 32) * 2 + par] = fmaxf(uu1 - vc1, 0.0f);
        }
        __syncwarp();

        // ---- single gemm pass over 8 pairs (16 edges), W2 read once ----
        unsigned long long acc[8][2];
#pragma unroll
        for (int p = 0; p < 8; p++) { acc[p][0] = 0ull; acc[p][1] = 0ull; }

#pragma unroll
        for (int q = 0; q < 16; q++) {
            const float4 wa = w2a[q * 32 + lane];
            const float4 wb = w2b[q * 32 + lane];
            const unsigned long long pa0 = pack2(wa.x, wa.x), pa1 = pack2(wa.y, wa.y);
            const unsigned long long pa2 = pack2(wa.z, wa.z), pa3 = pack2(wa.w, wa.w);
            const unsigned long long pb0 = pack2(wb.x, wb.x), pb1 = pack2(wb.y, wb.y);
            const unsigned long long pb2 = pack2(wb.z, wb.z), pb3 = pack2(wb.w, wb.w);
#pragma unroll
            for (int p = 0; p < 8; p++) {
                const float* tp = tb + p * 128 + 8 * q;
                const ulonglong2 t01 = *reinterpret_cast<const ulonglong2*>(tp);
                const ulonglong2 t23 = *reinterpret_cast<const ulonglong2*>(tp + 4);
                fma2(acc[p][0], t01.x, pa0);
                fma2(acc[p][0], t01.y, pa1);
                fma2(acc[p][0], t23.x, pa2);
                fma2(acc[p][0], t23.y, pa3);
                fma2(acc[p][1], t01.x, pb0);
                fma2(acc[p][1], t01.y, pb1);
                fma2(acc[p][1], t23.x, pb2);
                fma2(acc[p][1], t23.y, pb3);
            }
        }

        // ---- flush: running per-dst max -> atomics ----
#pragma unroll
        for (int p = 0; p < 8; p++) {
            float hea, hoa, heb, hob;
            unpack2(acc[p][0], hea, hoa);       // (even, odd) edge, channel lane
            unpack2(acc[p][1], heb, hob);       // (even, odd) edge, channel lane+32
#pragma unroll
            for (int par = 0; par < 2; par++) {
                const int e = p * 2 + par;
                if (!((mask >> e) & 1u)) continue;
                const float h0 = (par ? hoa : hea) + b2a;
                const float h1 = (par ? hob : heb) + b2b;
                const int d = six[e].y;         // broadcast LDS
                if (d != cur) {
                    if (cur >= 0) {
                        atomicMaxF(&out[(size_t)cur * 64 + lane],      m0);
                        atomicMaxF(&out[(size_t)cur * 64 + 32 + lane], m1);
                    }
                    cur = d;
                    m0 = -3.4e38f; m1 = -3.4e38f;
                }
                m0 = fmaxf(m0, h0);
                m1 = fmaxf(m1, h1);
            }
        }
    }
    if (cur >= 0) {
        atomicMaxF(&out[(size_t)cur * 64 + lane],      m0);
        atomicMaxF(&out[(size_t)cur * 64 + 32 + lane], m1);
    }
}

// ---------------------------------------------------------------------------
// Kernel 3: pos + batch (as float) tail of the flattened tuple output.
// ---------------------------------------------------------------------------
__global__ void tail_kernel(const float* __restrict__ pos,
                            const int* __restrict__ batch,
                            float* __restrict__ out, int tail)
{
    int i = blockIdx.x * blockDim.x + threadIdx.x;
    if (i >= tail) return;
    float v;
    if (i < NNODES * 3) v = pos[i];
    else {
        int k = i - NNODES * 3;
        v = (k < NNODES) ? (float)batch[k] : 0.0f;
    }
    out[NNODES * 64 + i] = v;
}

extern "C" void kernel_launch(void* const* d_in, const int* in_sizes, int n_in,
                              void* d_out, int out_size) {
    const float* x     = (const float*)d_in[0];
    const float* pos   = (const float*)d_in[1];
    const int*   batch = (const int*)d_in[2];
    const int*   ei    = (const int*)d_in[3];
    const float* W1    = (const float*)d_in[4];
    const float* b1    = (const float*)d_in[5];
    const float* W2    = (const float*)d_in[6];
    const float* b2    = (const float*)d_in[7];
    float* out = (float*)d_out;

    const long long E = (long long)in_sizes[3] / 2;

    cudaFuncSetAttribute(edge_kernel, cudaFuncAttributeMaxDynamicSharedMemorySize, 33280);

    node_kernel<<<296, 256>>>(x, pos, W1, b1, W2, b2, out);
    edge_kernel<<<740, 128, 33280>>>(ei, E, W2, b2, out);

    int tail = out_size - NNODES * 64;
    if (tail > 0) tail_kernel<<<(tail + 255) / 256, 256>>>(pos, batch, out, tail);
}

// round 11
// speedup vs baseline: 4.5732x; 1.2434x over previous
#include <cuda_runtime.h>
#include <cstdint>

#define NNODES 32768
#define EB 8     // node-kernel batch
#define ET 16    // edge-kernel tile (8 fma2-packed edge pairs, ONE gemm pass)

__device__ float g_u[NNODES * 64];   // g_a[n] + pos[n]·W1r
__device__ float g_v[NNODES * 64];   // pos[n]·W1r
__device__ long long g_Ereal;        // boundary of the real-edge prefix

__device__ __forceinline__ void atomicMaxF(float* addr, float v) {
    if (v >= 0.0f) atomicMax((int*)addr, __float_as_int(v));
    else           atomicMin((unsigned int*)addr, __float_as_uint(v));
}
__device__ __forceinline__ unsigned long long pack2(float lo, float hi) {
    unsigned long long r;
    asm("mov.b64 %0, {%1,%2};" : "=l"(r) : "f"(lo), "f"(hi));
    return r;
}
__device__ __forceinline__ void unpack2(unsigned long long p, float& lo, float& hi) {
    asm("mov.b64 {%0,%1}, %2;" : "=f"(lo), "=f"(hi) : "l"(p));
}
__device__ __forceinline__ void fma2(unsigned long long& acc,
                                     unsigned long long a, unsigned long long b) {
    asm("fma.rn.f32x2 %0, %1, %2, %3;" : "=l"(acc) : "l"(a), "l"(b), "l"(acc));
}

// W2 staged k-pair-major: w2a[q*32+j] = {W2[4q..4q+3][j]}, w2b same for j+32
__device__ __forceinline__ void stage_w2(const float* __restrict__ W2,
                                         float4* w2a, float4* w2b, int tid, int nthr) {
    for (int idx = tid; idx < 16 * 32; idx += nthr) {
        const int q = idx >> 5, j = idx & 31;
        const float* r0 = W2 + (4 * q) * 64;
        w2a[idx] = make_float4(r0[j],      r0[64 + j],      r0[128 + j],      r0[192 + j]);
        w2b[idx] = make_float4(r0[j + 32], r0[64 + j + 32], r0[128 + j + 32], r0[192 + j + 32]);
    }
}

// ---------------------------------------------------------------------------
// Kernel 0: find the first index where src==dst (start of the trivial
// self-loop/pad suffix). Predicate is monotone by construction of the list.
// ---------------------------------------------------------------------------
__global__ void bsearch_kernel(const int* __restrict__ ei, long long E) {
    if (threadIdx.x != 0 || blockIdx.x != 0) return;
    long long lo = 0, hi = E;
    while (lo < hi) {
        const long long mid = (lo + hi) >> 1;
        if (ei[mid] == ei[E + mid]) hi = mid; else lo = mid + 1;
    }
    g_Ereal = lo;
}

// ---------------------------------------------------------------------------
// Kernel 1: per-node. t = x@W1[0:4]+b1 ; v = pos·W1r ; u = t+v.
// Stores u,v; initializes out with the self-loop value relu(t)@W2 + b2.
// ---------------------------------------------------------------------------
__global__ void __launch_bounds__(256, 2) node_kernel(
    const float* __restrict__ x, const float* __restrict__ pos,
    const float* __restrict__ W1, const float* __restrict__ b1,
    const float* __restrict__ W2, const float* __restrict__ b2,
    float* __restrict__ out)
{
    __shared__ float4 w2a[16 * 32];
    __shared__ float4 w2b[16 * 32];
    __shared__ __align__(16) float tds[8][EB * 64];

    const int tid = threadIdx.x, lane = tid & 31, w = tid >> 5;
    stage_w2(W2, w2a, w2b, tid, 256);
    __syncthreads();
    float* td = tds[w];

    float wxa[4], wxb[4];
#pragma unroll
    for (int i = 0; i < 4; i++) { wxa[i] = W1[i * 64 + lane]; wxb[i] = W1[i * 64 + lane + 32]; }
    const float wra0 = W1[4 * 64 + lane],      wra1 = W1[5 * 64 + lane],      wra2 = W1[6 * 64 + lane];
    const float wrb0 = W1[4 * 64 + lane + 32], wrb1 = W1[5 * 64 + lane + 32], wrb2 = W1[6 * 64 + lane + 32];
    const float b1a = b1[lane], b1b = b1[lane + 32];
    const float b2a = b2[lane], b2b = b2[lane + 32];

    const int gw = blockIdx.x * 8 + w, nW = gridDim.x * 8;
    const int perWarp = (NNODES + nW - 1) / nW;
    const int n0 = gw * perWarp;
    int n1 = n0 + perWarp; if (n1 > NNODES) n1 = NNODES;

    for (int base = n0; base < n1; base += EB) {
        const int nb = min(EB, n1 - base);
        __syncwarp();
#pragma unroll
        for (int i = 0; i < EB; i++) {
            if (i >= nb) break;
            const int n = base + i;
            const float x0 = x[n * 4 + 0], x1 = x[n * 4 + 1];
            const float x2 = x[n * 4 + 2], x3 = x[n * 4 + 3];
            float t0 = fmaf(x3, wxa[3], fmaf(x2, wxa[2], fmaf(x1, wxa[1], fmaf(x0, wxa[0], b1a))));
            float t1 = fmaf(x3, wxb[3], fmaf(x2, wxb[2], fmaf(x1, wxb[1], fmaf(x0, wxb[0], b1b))));
            const float p0 = pos[n * 3 + 0], p1 = pos[n * 3 + 1], p2 = pos[n * 3 + 2];
            const float v0 = fmaf(p2, wra2, fmaf(p1, wra1, p0 * wra0));
            const float v1 = fmaf(p2, wrb2, fmaf(p1, wrb1, p0 * wrb0));
            g_v[(size_t)n * 64 + lane]      = v0;
            g_v[(size_t)n * 64 + 32 + lane] = v1;
            g_u[(size_t)n * 64 + lane]      = t0 + v0;
            g_u[(size_t)n * 64 + 32 + lane] = t1 + v1;
            td[i * 64 + lane]      = fmaxf(t0, 0.0f);
            td[i * 64 + lane + 32] = fmaxf(t1, 0.0f);
        }
        __syncwarp();

        unsigned long long acc[EB][2];
#pragma unroll
        for (int i = 0; i < EB; i++) { acc[i][0] = 0ull; acc[i][1] = 0ull; }
#pragma unroll
        for (int q = 0; q < 16; q++) {
            const ulonglong2 wa = *reinterpret_cast<const ulonglong2*>(&w2a[q * 32 + lane]);
            const ulonglong2 wb = *reinterpret_cast<const ulonglong2*>(&w2b[q * 32 + lane]);
#pragma unroll
            for (int i = 0; i < EB; i++) {
                const ulonglong2 tq = *reinterpret_cast<const ulonglong2*>(&td[i * 64 + q * 4]);
                fma2(acc[i][0], tq.x, wa.x);
                fma2(acc[i][0], tq.y, wa.y);
                fma2(acc[i][1], tq.x, wb.x);
                fma2(acc[i][1], tq.y, wb.y);
            }
        }
#pragma unroll
        for (int i = 0; i < EB; i++) {
            if (i >= nb) break;
            float a, b, c, d;
            unpack2(acc[i][0], a, b);
            unpack2(acc[i][1], c, d);
            const int n = base + i;
            out[(size_t)n * 64 + lane]      = a + b + b2a;
            out[(size_t)n * 64 + 32 + lane] = c + d + b2b;
        }
    }
}

// ---------------------------------------------------------------------------
// Kernel 2: per-edge over [0, g_Ereal) only (trivial suffix excluded).
// 16 edges/tile, one gemm pass via fma2 edge-pair packing; indices in smem.
// ---------------------------------------------------------------------------
__global__ void __launch_bounds__(128, 5) edge_kernel(
    const int* __restrict__ ei, long long E,
    const float* __restrict__ W2, const float* __restrict__ b2,
    float* __restrict__ out)
{
    extern __shared__ char smem[];
    float4* w2a  = (float4*)smem;                 //  8 KB
    float4* w2b  = (float4*)(smem + 8192);        //  8 KB
    float*  tds  = (float*)(smem + 16384);        // 16 KB: 4 warps x 8 pairs x 128
    int2*   sidx = (int2*)(smem + 32768);         // 512 B: 4 warps x 16

    const int tid = threadIdx.x, lane = tid & 31, w = tid >> 5;
    const unsigned FULL = 0xffffffffu;
    stage_w2(W2, w2a, w2b, tid, 128);
    __syncthreads();

    float* tb = tds + w * 1024;
    int2*  six = sidx + w * 16;

    const float b2a = b2[lane], b2b = b2[lane + 32];
    const int* __restrict__ srcA = ei;
    const int* __restrict__ dstA = ei + E;

    const long long Er = g_Ereal;                 // real-edge prefix only
    const long long gw = blockIdx.x * 4 + w;
    const long long nW = (long long)gridDim.x * 4;
    long long chunk = (Er + nW - 1) / nW;
    chunk = (chunk + ET - 1) / ET * ET;
    const long long e0 = gw * chunk;
    long long e1 = e0 + chunk; if (e1 > Er) e1 = Er;
    if (e0 >= e1) return;

    int cur = -1;
    float m0 = -3.4e38f, m1 = -3.4e38f;
    int dprev = -1;
    float vc0 = 0.0f, vc1 = 0.0f;

    for (long long base = e0; base < e1; base += ET) {
        __syncwarp();   // protect six / tb reuse across iterations

        // ---- index load: lanes 0-15, coalesced; out-of-range -> (0,0) self ----
        int sL = 0, dL = 0;
        if (lane < ET) {
            const long long e = base + lane;
            if (e < e1) { sL = srcA[e]; dL = dstA[e]; }
            six[lane] = make_int2(sL, dL);
        }
        const unsigned mask = __ballot_sync(FULL, (lane < ET) && (sL != dL));
        if (!mask) continue;                    // safety net (shouldn't trigger now)
        __syncwarp();

        // ---- t-phase: t = relu(u[s] - v[d]), v segment-cached; pair-interleaved ----
#pragma unroll
        for (int i = 0; i < ET; i++) {
            const int2 sd = six[i];             // broadcast LDS
            if (sd.y != dprev) {                // warp-uniform
                vc0 = g_v[(size_t)sd.y * 64 + lane];
                vc1 = g_v[(size_t)sd.y * 64 + 32 + lane];
                dprev = sd.y;
            }
            const float uu0 = g_u[(size_t)sd.x * 64 + lane];
            const float uu1 = g_u[(size_t)sd.x * 64 + 32 + lane];
            const int p = i >> 1, par = i & 1;
            tb[p * 128 + lane * 2 + par]        = fmaxf(uu0 - vc0, 0.0f);
            tb[p * 128 + (lane + 32) * 2 + par] = fmaxf(uu1 - vc1, 0.0f);
        }
        __syncwarp();

        // ---- single gemm pass over 8 pairs (16 edges), W2 read once ----
        unsigned long long acc[8][2];
#pragma unroll
        for (int p = 0; p < 8; p++) { acc[p][0] = 0ull; acc[p][1] = 0ull; }

#pragma unroll
        for (int q = 0; q < 16; q++) {
            const float4 wa = w2a[q * 32 + lane];
            const float4 wb = w2b[q * 32 + lane];
            const unsigned long long pa0 = pack2(wa.x, wa.x), pa1 = pack2(wa.y, wa.y);
            const unsigned long long pa2 = pack2(wa.z, wa.z), pa3 = pack2(wa.w, wa.w);
            const unsigned long long pb0 = pack2(wb.x, wb.x), pb1 = pack2(wb.y, wb.y);
            const unsigned long long pb2 = pack2(wb.z, wb.z), pb3 = pack2(wb.w, wb.w);
#pragma unroll
            for (int p = 0; p < 8; p++) {
                const float* tp = tb + p * 128 + 8 * q;
                const ulonglong2 t01 = *reinterpret_cast<const ulonglong2*>(tp);
                const ulonglong2 t23 = *reinterpret_cast<const ulonglong2*>(tp + 4);
                fma2(acc[p][0], t01.x, pa0);
                fma2(acc[p][0], t01.y, pa1);
                fma2(acc[p][0], t23.x, pa2);
                fma2(acc[p][0], t23.y, pa3);
                fma2(acc[p][1], t01.x, pb0);
                fma2(acc[p][1], t01.y, pb1);
                fma2(acc[p][1], t23.x, pb2);
                fma2(acc[p][1], t23.y, pb3);
            }
        }

        // ---- flush: running per-dst max -> atomics ----
#pragma unroll
        for (int p = 0; p < 8; p++) {
            float hea, hoa, heb, hob;
            unpack2(acc[p][0], hea, hoa);       // (even, odd) edge, channel lane
            unpack2(acc[p][1], heb, hob);       // (even, odd) edge, channel lane+32
#pragma unroll
            for (int par = 0; par < 2; par++) {
                const int e = p * 2 + par;
                if (!((mask >> e) & 1u)) continue;
                const float h0 = (par ? hoa : hea) + b2a;
                const float h1 = (par ? hob : heb) + b2b;
                const int d = six[e].y;         // broadcast LDS
                if (d != cur) {
                    if (cur >= 0) {
                        atomicMaxF(&out[(size_t)cur * 64 + lane],      m0);
                        atomicMaxF(&out[(size_t)cur * 64 + 32 + lane], m1);
                    }
                    cur = d;
                    m0 = -3.4e38f; m1 = -3.4e38f;
                }
                m0 = fmaxf(m0, h0);
                m1 = fmaxf(m1, h1);
            }
        }
    }
    if (cur >= 0) {
        atomicMaxF(&out[(size_t)cur * 64 + lane],      m0);
        atomicMaxF(&out[(size_t)cur * 64 + 32 + lane], m1);
    }
}

// ---------------------------------------------------------------------------
// Kernel 3: pos + batch (as float) tail of the flattened tuple output.
// ---------------------------------------------------------------------------
__global__ void tail_kernel(const float* __restrict__ pos,
                            const int* __restrict__ batch,
                            float* __restrict__ out, int tail)
{
    int i = blockIdx.x * blockDim.x + threadIdx.x;
    if (i >= tail) return;
    float v;
    if (i < NNODES * 3) v = pos[i];
    else {
        int k = i - NNODES * 3;
        v = (k < NNODES) ? (float)batch[k] : 0.0f;
    }
    out[NNODES * 64 + i] = v;
}

extern "C" void kernel_launch(void* const* d_in, const int* in_sizes, int n_in,
                              void* d_out, int out_size) {
    const float* x     = (const float*)d_in[0];
    const float* pos   = (const float*)d_in[1];
    const int*   batch = (const int*)d_in[2];
    const int*   ei    = (const int*)d_in[3];
    const float* W1    = (const float*)d_in[4];
    const float* b1    = (const float*)d_in[5];
    const float* W2    = (const float*)d_in[6];
    const float* b2    = (const float*)d_in[7];
    float* out = (float*)d_out;

    const long long E = (long long)in_sizes[3] / 2;

    cudaFuncSetAttribute(edge_kernel, cudaFuncAttributeMaxDynamicSharedMemorySize, 33280);

    bsearch_kernel<<<1, 32>>>(ei, E);
    node_kernel<<<296, 256>>>(x, pos, W1, b1, W2, b2, out);
    edge_kernel<<<740, 128, 33280>>>(ei, E, W2, b2, out);

    int tail = out_size - NNODES * 64;
    if (tail > 0) tail_kernel<<<(tail + 255) / 256, 256>>>(pos, batch, out, tail);
}

// round 12
// speedup vs baseline: 4.7646x; 1.0419x over previous
#include <cuda_runtime.h>
#include <cstdint>

#define NNODES 32768
#define EB 8     // node-kernel batch
#define ET 16    // edge-kernel tile (8 fma2-packed edge pairs, ONE gemm pass)

__device__ float g_u[NNODES * 64];   // g_a[n] + pos[n]·W1r
__device__ float g_v[NNODES * 64];   // pos[n]·W1r
__device__ long long g_Ereal;        // boundary of the real-edge prefix

__device__ __forceinline__ void atomicMaxF(float* addr, float v) {
    if (v >= 0.0f) atomicMax((int*)addr, __float_as_int(v));
    else           atomicMin((unsigned int*)addr, __float_as_uint(v));
}
__device__ __forceinline__ unsigned long long pack2(float lo, float hi) {
    unsigned long long r;
    asm("mov.b64 %0, {%1,%2};" : "=l"(r) : "f"(lo), "f"(hi));
    return r;
}
__device__ __forceinline__ void unpack2(unsigned long long p, float& lo, float& hi) {
    asm("mov.b64 {%0,%1}, %2;" : "=f"(lo), "=f"(hi) : "l"(p));
}
__device__ __forceinline__ void fma2(unsigned long long& acc,
                                     unsigned long long a, unsigned long long b) {
    asm("fma.rn.f32x2 %0, %1, %2, %3;" : "=l"(acc) : "l"(a), "l"(b), "l"(acc));
}

// W2 staged k-pair-major: w2a[q*32+j] = {W2[4q..4q+3][j]}, w2b same for j+32
__device__ __forceinline__ void stage_w2(const float* __restrict__ W2,
                                         float4* w2a, float4* w2b, int tid, int nthr) {
    for (int idx = tid; idx < 16 * 32; idx += nthr) {
        const int q = idx >> 5, j = idx & 31;
        const float* r0 = W2 + (4 * q) * 64;
        w2a[idx] = make_float4(r0[j],      r0[64 + j],      r0[128 + j],      r0[192 + j]);
        w2b[idx] = make_float4(r0[j + 32], r0[64 + j + 32], r0[128 + j + 32], r0[192 + j + 32]);
    }
}

// ---------------------------------------------------------------------------
// Kernel 0: fused warp-parallel bsearch (block 0, warp 0) + tail copy (all).
// Finds the first index where src==dst (monotone by construction).
// ---------------------------------------------------------------------------
__global__ void pre_kernel(const int* __restrict__ ei, long long E,
                           const float* __restrict__ pos,
                           const int* __restrict__ batch,
                           float* __restrict__ out, int tail)
{
    if (blockIdx.x == 0 && threadIdx.x < 32) {
        const int lane = threadIdx.x;
        long long lo = -1, hi = E;            // pred(lo)=false, pred(hi)=true invariant
        while (hi - lo > 1) {
            const long long step = (hi - lo) / 32 + 1;
            const long long p = lo + (long long)(lane + 1) * step;
            bool pr = true;
            if (p < hi) pr = (ei[p] == ei[E + p]);
            const unsigned b = __ballot_sync(0xffffffffu, pr);
            const int k = __ffs(b) - 1;        // b != 0 guaranteed (lane 31 out of range)
            const long long nhi = lo + (long long)(k + 1) * step;
            lo = lo + (long long)k * step;
            hi = nhi < hi ? nhi : hi;
        }
        if (lane == 0) g_Ereal = hi;
    }
    for (int i = blockIdx.x * blockDim.x + threadIdx.x; i < tail;
         i += gridDim.x * blockDim.x) {
        float v;
        if (i < NNODES * 3) v = pos[i];
        else {
            const int k = i - NNODES * 3;
            v = (k < NNODES) ? (float)batch[k] : 0.0f;
        }
        out[NNODES * 64 + i] = v;
    }
}

// ---------------------------------------------------------------------------
// Kernel 1: per-node. t = x@W1[0:4]+b1 ; v = pos·W1r ; u = t+v.
// Stores u,v; initializes out with the self-loop value relu(t)@W2 + b2.
// ---------------------------------------------------------------------------
__global__ void __launch_bounds__(256, 2) node_kernel(
    const float* __restrict__ x, const float* __restrict__ pos,
    const float* __restrict__ W1, const float* __restrict__ b1,
    const float* __restrict__ W2, const float* __restrict__ b2,
    float* __restrict__ out)
{
    __shared__ float4 w2a[16 * 32];
    __shared__ float4 w2b[16 * 32];
    __shared__ __align__(16) float tds[8][EB * 64];

    const int tid = threadIdx.x, lane = tid & 31, w = tid >> 5;
    stage_w2(W2, w2a, w2b, tid, 256);
    __syncthreads();
    float* td = tds[w];

    float wxa[4], wxb[4];
#pragma unroll
    for (int i = 0; i < 4; i++) { wxa[i] = W1[i * 64 + lane]; wxb[i] = W1[i * 64 + lane + 32]; }
    const float wra0 = W1[4 * 64 + lane],      wra1 = W1[5 * 64 + lane],      wra2 = W1[6 * 64 + lane];
    const float wrb0 = W1[4 * 64 + lane + 32], wrb1 = W1[5 * 64 + lane + 32], wrb2 = W1[6 * 64 + lane + 32];
    const float b1a = b1[lane], b1b = b1[lane + 32];
    const float b2a = b2[lane], b2b = b2[lane + 32];

    const int gw = blockIdx.x * 8 + w, nW = gridDim.x * 8;
    const int perWarp = (NNODES + nW - 1) / nW;
    const int n0 = gw * perWarp;
    int n1 = n0 + perWarp; if (n1 > NNODES) n1 = NNODES;

    for (int base = n0; base < n1; base += EB) {
        const int nb = min(EB, n1 - base);
        __syncwarp();
#pragma unroll
        for (int i = 0; i < EB; i++) {
            if (i >= nb) break;
            const int n = base + i;
            const float x0 = x[n * 4 + 0], x1 = x[n * 4 + 1];
            const float x2 = x[n * 4 + 2], x3 = x[n * 4 + 3];
            float t0 = fmaf(x3, wxa[3], fmaf(x2, wxa[2], fmaf(x1, wxa[1], fmaf(x0, wxa[0], b1a))));
            float t1 = fmaf(x3, wxb[3], fmaf(x2, wxb[2], fmaf(x1, wxb[1], fmaf(x0, wxb[0], b1b))));
            const float p0 = pos[n * 3 + 0], p1 = pos[n * 3 + 1], p2 = pos[n * 3 + 2];
            const float v0 = fmaf(p2, wra2, fmaf(p1, wra1, p0 * wra0));
            const float v1 = fmaf(p2, wrb2, fmaf(p1, wrb1, p0 * wrb0));
            g_v[(size_t)n * 64 + lane]      = v0;
            g_v[(size_t)n * 64 + 32 + lane] = v1;
            g_u[(size_t)n * 64 + lane]      = t0 + v0;
            g_u[(size_t)n * 64 + 32 + lane] = t1 + v1;
            td[i * 64 + lane]      = fmaxf(t0, 0.0f);
            td[i * 64 + lane + 32] = fmaxf(t1, 0.0f);
        }
        __syncwarp();

        unsigned long long acc[EB][2];
#pragma unroll
        for (int i = 0; i < EB; i++) { acc[i][0] = 0ull; acc[i][1] = 0ull; }
#pragma unroll
        for (int q = 0; q < 16; q++) {
            const ulonglong2 wa = *reinterpret_cast<const ulonglong2*>(&w2a[q * 32 + lane]);
            const ulonglong2 wb = *reinterpret_cast<const ulonglong2*>(&w2b[q * 32 + lane]);
#pragma unroll
            for (int i = 0; i < EB; i++) {
                const ulonglong2 tq = *reinterpret_cast<const ulonglong2*>(&td[i * 64 + q * 4]);
                fma2(acc[i][0], tq.x, wa.x);
                fma2(acc[i][0], tq.y, wa.y);
                fma2(acc[i][1], tq.x, wb.x);
                fma2(acc[i][1], tq.y, wb.y);
            }
        }
#pragma unroll
        for (int i = 0; i < EB; i++) {
            if (i >= nb) break;
            float a, b, c, d;
            unpack2(acc[i][0], a, b);
            unpack2(acc[i][1], c, d);
            const int n = base + i;
            out[(size_t)n * 64 + lane]      = a + b + b2a;
            out[(size_t)n * 64 + 32 + lane] = c + d + b2b;
        }
    }
}

// ---------------------------------------------------------------------------
// Kernel 2: per-edge over [0, g_Ereal). 16 edges/tile, one gemm pass via
// fma2 edge-pair packing; indices in smem; full-mask fast path in flush.
// ---------------------------------------------------------------------------
__global__ void __launch_bounds__(128, 5) edge_kernel(
    const int* __restrict__ ei, long long E,
    const float* __restrict__ W2, const float* __restrict__ b2,
    float* __restrict__ out)
{
    extern __shared__ char smem[];
    float4* w2a  = (float4*)smem;                 //  8 KB
    float4* w2b  = (float4*)(smem + 8192);        //  8 KB
    float*  tds  = (float*)(smem + 16384);        // 16 KB: 4 warps x 8 pairs x 128
    int2*   sidx = (int2*)(smem + 32768);         // 512 B: 4 warps x 16

    const int tid = threadIdx.x, lane = tid & 31, w = tid >> 5;
    const unsigned FULL = 0xffffffffu;
    stage_w2(W2, w2a, w2b, tid, 128);
    __syncthreads();

    float* tb = tds + w * 1024;
    int2*  six = sidx + w * 16;

    const float b2a = b2[lane], b2b = b2[lane + 32];
    const int* __restrict__ srcA = ei;
    const int* __restrict__ dstA = ei + E;

    const long long Er = g_Ereal;                 // real-edge prefix only
    const long long gw = blockIdx.x * 4 + w;
    const long long nW = (long long)gridDim.x * 4;
    long long chunk = (Er + nW - 1) / nW;
    chunk = (chunk + ET - 1) / ET * ET;
    const long long e0 = gw * chunk;
    long long e1 = e0 + chunk; if (e1 > Er) e1 = Er;
    if (e0 >= e1) return;

    int cur = -1;
    float m0 = -3.4e38f, m1 = -3.4e38f;
    int dprev = -1;
    float vc0 = 0.0f, vc1 = 0.0f;

    for (long long base = e0; base < e1; base += ET) {
        __syncwarp();   // protect six / tb reuse across iterations

        // ---- index load: lanes 0-15, coalesced; out-of-range -> (0,0) self ----
        int sL = 0, dL = 0;
        if (lane < ET) {
            const long long e = base + lane;
            if (e < e1) { sL = srcA[e]; dL = dstA[e]; }
            six[lane] = make_int2(sL, dL);
        }
        const unsigned mask = __ballot_sync(FULL, (lane < ET) && (sL != dL));
        if (!mask) continue;                    // safety net
        __syncwarp();

        // ---- t-phase: t = relu(u[s] - v[d]), v segment-cached; pair-interleaved ----
#pragma unroll
        for (int i = 0; i < ET; i++) {
            const int2 sd = six[i];             // broadcast LDS
            if (sd.y != dprev) {                // warp-uniform
                vc0 = g_v[(size_t)sd.y * 64 + lane];
                vc1 = g_v[(size_t)sd.y * 64 + 32 + lane];
                dprev = sd.y;
            }
            const float uu0 = g_u[(size_t)sd.x * 64 + lane];
            const float uu1 = g_u[(size_t)sd.x * 64 + 32 + lane];
            const int p = i >> 1, par = i & 1;
            tb[p * 128 + lane * 2 + par]        = fmaxf(uu0 - vc0, 0.0f);
            tb[p * 128 + (lane + 32) * 2 + par] = fmaxf(uu1 - vc1, 0.0f);
        }
        __syncwarp();

        // ---- single gemm pass over 8 pairs (16 edges), W2 read once ----
        unsigned long long acc[8][2];
#pragma unroll
        for (int p = 0; p < 8; p++) { acc[p][0] = 0ull; acc[p][1] = 0ull; }

#pragma unroll
        for (int q = 0; q < 16; q++) {
            const float4 wa = w2a[q * 32 + lane];
            const float4 wb = w2b[q * 32 + lane];
            const unsigned long long pa0 = pack2(wa.x, wa.x), pa1 = pack2(wa.y, wa.y);
            const unsigned long long pa2 = pack2(wa.z, wa.z), pa3 = pack2(wa.w, wa.w);
            const unsigned long long pb0 = pack2(wb.x, wb.x), pb1 = pack2(wb.y, wb.y);
            const unsigned long long pb2 = pack2(wb.z, wb.z), pb3 = pack2(wb.w, wb.w);
#pragma unroll
            for (int p = 0; p < 8; p++) {
                const float* tp = tb + p * 128 + 8 * q;
                const ulonglong2 t01 = *reinterpret_cast<const ulonglong2*>(tp);
                const ulonglong2 t23 = *reinterpret_cast<const ulonglong2*>(tp + 4);
                fma2(acc[p][0], t01.x, pa0);
                fma2(acc[p][0], t01.y, pa1);
                fma2(acc[p][0], t23.x, pa2);
                fma2(acc[p][0], t23.y, pa3);
                fma2(acc[p][1], t01.x, pb0);
                fma2(acc[p][1], t01.y, pb1);
                fma2(acc[p][1], t23.x, pb2);
                fma2(acc[p][1], t23.y, pb3);
            }
        }

        // ---- flush: running per-dst max -> atomics ----
        if (mask == 0xFFFFu) {
            // fast path: every edge real (the common case in the prefix)
#pragma unroll
            for (int p = 0; p < 8; p++) {
                float hea, hoa, heb, hob;
                unpack2(acc[p][0], hea, hoa);
                unpack2(acc[p][1], heb, hob);
#pragma unroll
                for (int par = 0; par < 2; par++) {
                    const float h0 = (par ? hoa : hea) + b2a;
                    const float h1 = (par ? hob : heb) + b2b;
                    const int d = six[p * 2 + par].y;
                    if (d != cur) {
                        if (cur >= 0) {
                            atomicMaxF(&out[(size_t)cur * 64 + lane],      m0);
                            atomicMaxF(&out[(size_t)cur * 64 + 32 + lane], m1);
                        }
                        cur = d;
                        m0 = -3.4e38f; m1 = -3.4e38f;
                    }
                    m0 = fmaxf(m0, h0);
                    m1 = fmaxf(m1, h1);
                }
            }
        } else {
#pragma unroll
            for (int p = 0; p < 8; p++) {
                float hea, hoa, heb, hob;
                unpack2(acc[p][0], hea, hoa);
                unpack2(acc[p][1], heb, hob);
#pragma unroll
                for (int par = 0; par < 2; par++) {
                    const int e = p * 2 + par;
                    if (!((mask >> e) & 1u)) continue;
                    const float h0 = (par ? hoa : hea) + b2a;
                    const float h1 = (par ? hob : heb) + b2b;
                    const int d = six[e].y;
                    if (d != cur) {
                        if (cur >= 0) {
                            atomicMaxF(&out[(size_t)cur * 64 + lane],      m0);
                            atomicMaxF(&out[(size_t)cur * 64 + 32 + lane], m1);
                        }
                        cur = d;
                        m0 = -3.4e38f; m1 = -3.4e38f;
                    }
                    m0 = fmaxf(m0, h0);
                    m1 = fmaxf(m1, h1);
                }
            }
        }
    }
    if (cur >= 0) {
        atomicMaxF(&out[(size_t)cur * 64 + lane],      m0);
        atomicMaxF(&out[(size_t)cur * 64 + 32 + lane], m1);
    }
}

extern "C" void kernel_launch(void* const* d_in, const int* in_sizes, int n_in,
                              void* d_out, int out_size) {
    const float* x     = (const float*)d_in[0];
    const float* pos   = (const float*)d_in[1];
    const int*   batch = (const int*)d_in[2];
    const int*   ei    = (const int*)d_in[3];
    const float* W1    = (const float*)d_in[4];
    const float* b1    = (const float*)d_in[5];
    const float* W2    = (const float*)d_in[6];
    const float* b2    = (const float*)d_in[7];
    float* out = (float*)d_out;

    const long long E = (long long)in_sizes[3] / 2;

    cudaFuncSetAttribute(edge_kernel, cudaFuncAttributeMaxDynamicSharedMemorySize, 33280);

    int tail = out_size - NNODES * 64;
    if (tail < 0) tail = 0;
    pre_kernel<<<128, 256>>>(ei, E, pos, batch, out, tail);
    node_kernel<<<296, 256>>>(x, pos, W1, b1, W2, b2, out);
    edge_kernel<<<740, 128, 33280>>>(ei, E, W2, b2, out);
}

// round 14
// speedup vs baseline: 4.8515x; 1.0182x over previous
#include <cuda_runtime.h>
#include <cstdint>

#define NNODES 32768
#define EB 8     // node-kernel batch
#define ET 16    // edge-kernel tile (8 fma2-packed edge pairs, ONE gemm pass)

__device__ float g_u[NNODES * 64];   // g_a[n] + pos[n]·W1r
__device__ float g_v[NNODES * 64];   // pos[n]·W1r
__device__ long long g_Ereal;        // boundary of the real-edge prefix

__device__ __forceinline__ void atomicMaxF(float* addr, float v) {
    if (v >= 0.0f) atomicMax((int*)addr, __float_as_int(v));
    else           atomicMin((unsigned int*)addr, __float_as_uint(v));
}
__device__ __forceinline__ unsigned long long pack2(float lo, float hi) {
    unsigned long long r;
    asm("mov.b64 %0, {%1,%2};" : "=l"(r) : "f"(lo), "f"(hi));
    return r;
}
__device__ __forceinline__ void unpack2(unsigned long long p, float& lo, float& hi) {
    asm("mov.b64 {%0,%1}, %2;" : "=f"(lo), "=f"(hi) : "l"(p));
}
__device__ __forceinline__ void fma2(unsigned long long& acc,
                                     unsigned long long a, unsigned long long b) {
    asm("fma.rn.f32x2 %0, %1, %2, %3;" : "=l"(acc) : "l"(a), "l"(b), "l"(acc));
}

// W2 staged k-pair-major: w2a[q*32+j] = {W2[4q..4q+3][j]}, w2b same for j+32
__device__ __forceinline__ void stage_w2(const float* __restrict__ W2,
                                         float4* w2a, float4* w2b, int tid, int nthr) {
    for (int idx = tid; idx < 16 * 32; idx += nthr) {
        const int q = idx >> 5, j = idx & 31;
        const float* r0 = W2 + (4 * q) * 64;
        w2a[idx] = make_float4(r0[j],      r0[64 + j],      r0[128 + j],      r0[192 + j]);
        w2b[idx] = make_float4(r0[j + 32], r0[64 + j + 32], r0[128 + j + 32], r0[192 + j + 32]);
    }
}

// ---------------------------------------------------------------------------
// Kernel 1: per-node + fused pre-work.
//   block 0 / warp 0: warp-parallel bsearch for the real-edge boundary.
//   all blocks: t = x@W1[0:4]+b1 ; v = pos·W1r ; u = t+v ; out init; then
//   grid-strided tail copy (pos, batch as float).
// ---------------------------------------------------------------------------
__global__ void __launch_bounds__(256, 2) node_kernel(
    const float* __restrict__ x, const float* __restrict__ pos,
    const float* __restrict__ W1, const float* __restrict__ b1,
    const float* __restrict__ W2, const float* __restrict__ b2,
    float* __restrict__ out,
    const int* __restrict__ ei, long long E,
    const int* __restrict__ batch, int tail)
{
    __shared__ float4 w2a[16 * 32];
    __shared__ float4 w2b[16 * 32];
    __shared__ __align__(16) float tds[8][EB * 64];

    const int tid = threadIdx.x, lane = tid & 31, w = tid >> 5;

    // -- fused bsearch: block 0, warp 0 (disjoint lifetime from main loop) --
    if (blockIdx.x == 0 && w == 0) {
        long long lo = -1, hi = E;            // pred(lo)=false, pred(hi)=true
        while (hi - lo > 1) {
            const long long step = (hi - lo) / 32 + 1;
            const long long p = lo + (long long)(lane + 1) * step;
            bool pr = true;
            if (p < hi) pr = (ei[p] == ei[E + p]);
            const unsigned b = __ballot_sync(0xffffffffu, pr);
            const int k = __ffs(b) - 1;        // b != 0 (lane 31 out of range)
            const long long nhi = lo + (long long)(k + 1) * step;
            lo = lo + (long long)k * step;
            hi = nhi < hi ? nhi : hi;
        }
        if (lane == 0) g_Ereal = hi;
    }

    stage_w2(W2, w2a, w2b, tid, 256);
    __syncthreads();
    float* td = tds[w];

    float wxa[4], wxb[4];
#pragma unroll
    for (int i = 0; i < 4; i++) { wxa[i] = W1[i * 64 + lane]; wxb[i] = W1[i * 64 + lane + 32]; }
    const float wra0 = W1[4 * 64 + lane],      wra1 = W1[5 * 64 + lane],      wra2 = W1[6 * 64 + lane];
    const float wrb0 = W1[4 * 64 + lane + 32], wrb1 = W1[5 * 64 + lane + 32], wrb2 = W1[6 * 64 + lane + 32];
    const float b1a = b1[lane], b1b = b1[lane + 32];
    const float b2a = b2[lane], b2b = b2[lane + 32];

    const int gw = blockIdx.x * 8 + w, nW = gridDim.x * 8;
    const int perWarp = (NNODES + nW - 1) / nW;
    const int n0 = gw * perWarp;
    int n1 = n0 + perWarp; if (n1 > NNODES) n1 = NNODES;

    for (int base = n0; base < n1; base += EB) {
        const int nb = min(EB, n1 - base);
        __syncwarp();
#pragma unroll
        for (int i = 0; i < EB; i++) {
            if (i >= nb) break;
            const int n = base + i;
            const float x0 = x[n * 4 + 0], x1 = x[n * 4 + 1];
            const float x2 = x[n * 4 + 2], x3 = x[n * 4 + 3];
            float t0 = fmaf(x3, wxa[3], fmaf(x2, wxa[2], fmaf(x1, wxa[1], fmaf(x0, wxa[0], b1a))));
            float t1 = fmaf(x3, wxb[3], fmaf(x2, wxb[2], fmaf(x1, wxb[1], fmaf(x0, wxb[0], b1b))));
            const float p0 = pos[n * 3 + 0], p1 = pos[n * 3 + 1], p2 = pos[n * 3 + 2];
            const float v0 = fmaf(p2, wra2, fmaf(p1, wra1, p0 * wra0));
            const float v1 = fmaf(p2, wrb2, fmaf(p1, wrb1, p0 * wrb0));
            g_v[(size_t)n * 64 + lane]      = v0;
            g_v[(size_t)n * 64 + 32 + lane] = v1;
            g_u[(size_t)n * 64 + lane]      = t0 + v0;
            g_u[(size_t)n * 64 + 32 + lane] = t1 + v1;
            td[i * 64 + lane]      = fmaxf(t0, 0.0f);
            td[i * 64 + lane + 32] = fmaxf(t1, 0.0f);
        }
        __syncwarp();

        unsigned long long acc[EB][2];
#pragma unroll
        for (int i = 0; i < EB; i++) { acc[i][0] = 0ull; acc[i][1] = 0ull; }
#pragma unroll
        for (int q = 0; q < 16; q++) {
            const ulonglong2 wa = *reinterpret_cast<const ulonglong2*>(&w2a[q * 32 + lane]);
            const ulonglong2 wb = *reinterpret_cast<const ulonglong2*>(&w2b[q * 32 + lane]);
#pragma unroll
            for (int i = 0; i < EB; i++) {
                const ulonglong2 tq = *reinterpret_cast<const ulonglong2*>(&td[i * 64 + q * 4]);
                fma2(acc[i][0], tq.x, wa.x);
                fma2(acc[i][0], tq.y, wa.y);
                fma2(acc[i][1], tq.x, wb.x);
                fma2(acc[i][1], tq.y, wb.y);
            }
        }
#pragma unroll
        for (int i = 0; i < EB; i++) {
            if (i >= nb) break;
            float a, b, c, d;
            unpack2(acc[i][0], a, b);
            unpack2(acc[i][1], c, d);
            const int n = base + i;
            out[(size_t)n * 64 + lane]      = a + b + b2a;
            out[(size_t)n * 64 + 32 + lane] = c + d + b2b;
        }
    }

    // -- fused tail copy (disjoint lifetime) --
    for (int i = blockIdx.x * blockDim.x + tid; i < tail; i += gridDim.x * blockDim.x) {
        float v;
        if (i < NNODES * 3) v = pos[i];
        else {
            const int k = i - NNODES * 3;
            v = (k < NNODES) ? (float)batch[k] : 0.0f;
        }
        out[NNODES * 64 + i] = v;
    }
}

// ---------------------------------------------------------------------------
// Kernel 2: per-edge over [0, g_Ereal). 16 edges/tile, one gemm pass via
// fma2 edge-pair packing; indices prefetched one tile ahead in registers.
// ---------------------------------------------------------------------------
__global__ void __launch_bounds__(128, 5) edge_kernel(
    const int* __restrict__ ei, long long E,
    const float* __restrict__ W2, const float* __restrict__ b2,
    float* __restrict__ out)
{
    extern __shared__ char smem[];
    float4* w2a  = (float4*)smem;                 //  8 KB
    float4* w2b  = (float4*)(smem + 8192);        //  8 KB
    float*  tds  = (float*)(smem + 16384);        // 16 KB: 4 warps x 8 pairs x 128
    int2*   sidx = (int2*)(smem + 32768);         // 512 B: 4 warps x 16

    const int tid = threadIdx.x, lane = tid & 31, w = tid >> 5;
    const unsigned FULL = 0xffffffffu;
    stage_w2(W2, w2a, w2b, tid, 128);
    __syncthreads();

    float* tb = tds + w * 1024;
    int2*  six = sidx + w * 16;

    const float b2a = b2[lane], b2b = b2[lane + 32];
    const int* __restrict__ srcA = ei;
    const int* __restrict__ dstA = ei + E;

    const long long Er = g_Ereal;                 // real-edge prefix only
    const long long gw = blockIdx.x * 4 + w;
    const long long nW = (long long)gridDim.x * 4;
    long long chunk = (Er + nW - 1) / nW;
    chunk = (chunk + ET - 1) / ET * ET;
    const long long e0 = gw * chunk;
    long long e1 = e0 + chunk; if (e1 > Er) e1 = Er;
    if (e0 >= e1) return;

    int cur = -1;
    float m0 = -3.4e38f, m1 = -3.4e38f;
    int dprev = -1;
    float vc0 = 0.0f, vc1 = 0.0f;

    // prologue: first tile's indices into registers
    int sL = 0, dL = 0;
    if (lane < ET) {
        const long long e = e0 + lane;
        if (e < e1) { sL = srcA[e]; dL = dstA[e]; }
    }

    for (long long base = e0; base < e1; base += ET) {
        __syncwarp();   // protect six / tb reuse across iterations

        if (lane < ET) six[lane] = make_int2(sL, dL);
        const unsigned mask = __ballot_sync(FULL, (lane < ET) && (sL != dL));

        // prefetch next tile's indices NOW; they age under the gemm
        {
            const long long e = base + ET + lane;
            sL = 0; dL = 0;
            if (lane < ET && e < e1) { sL = srcA[e]; dL = dstA[e]; }
        }
        if (!mask) continue;                    // safety net (boundary only)
        __syncwarp();

        // ---- t-phase: t = relu(u[s] - v[d]), v segment-cached; pair-interleaved ----
#pragma unroll
        for (int i = 0; i < ET; i++) {
            const int2 sd = six[i];             // broadcast LDS
            if (sd.y != dprev) {                // warp-uniform
                vc0 = g_v[(size_t)sd.y * 64 + lane];
                vc1 = g_v[(size_t)sd.y * 64 + 32 + lane];
                dprev = sd.y;
            }
            const float uu0 = g_u[(size_t)sd.x * 64 + lane];
            const float uu1 = g_u[(size_t)sd.x * 64 + 32 + lane];
            const int p = i >> 1, par = i & 1;
            tb[p * 128 + lane * 2 + par]        = fmaxf(uu0 - vc0, 0.0f);
            tb[p * 128 + (lane + 32) * 2 + par] = fmaxf(uu1 - vc1, 0.0f);
        }
        __syncwarp();

        // ---- single gemm pass over 8 pairs (16 edges), W2 read once ----
        unsigned long long acc[8][2];
#pragma unroll
        for (int p = 0; p < 8; p++) { acc[p][0] = 0ull; acc[p][1] = 0ull; }

#pragma unroll
        for (int q = 0; q < 16; q++) {
            const float4 wa = w2a[q * 32 + lane];
            const float4 wb = w2b[q * 32 + lane];
            const unsigned long long pa0 = pack2(wa.x, wa.x), pa1 = pack2(wa.y, wa.y);
            const unsigned long long pa2 = pack2(wa.z, wa.z), pa3 = pack2(wa.w, wa.w);
            const unsigned long long pb0 = pack2(wb.x, wb.x), pb1 = pack2(wb.y, wb.y);
            const unsigned long long pb2 = pack2(wb.z, wb.z), pb3 = pack2(wb.w, wb.w);
#pragma unroll
            for (int p = 0; p < 8; p++) {
                const float* tp = tb + p * 128 + 8 * q;
                const ulonglong2 t01 = *reinterpret_cast<const ulonglong2*>(tp);
                const ulonglong2 t23 = *reinterpret_cast<const ulonglong2*>(tp + 4);
                fma2(acc[p][0], t01.x, pa0);
                fma2(acc[p][0], t01.y, pa1);
                fma2(acc[p][0], t23.x, pa2);
                fma2(acc[p][0], t23.y, pa3);
                fma2(acc[p][1], t01.x, pb0);
                fma2(acc[p][1], t01.y, pb1);
                fma2(acc[p][1], t23.x, pb2);
                fma2(acc[p][1], t23.y, pb3);
            }
        }

        // ---- flush: running per-dst max -> atomics ----
        if (mask == 0xFFFFu) {
#pragma unroll
            for (int p = 0; p < 8; p++) {
                float hea, hoa, heb, hob;
                unpack2(acc[p][0], hea, hoa);
                unpack2(acc[p][1], heb, hob);
#pragma unroll
                for (int par = 0; par < 2; par++) {
                    const float h0 = (par ? hoa : hea) + b2a;
                    const float h1 = (par ? hob : heb) + b2b;
                    const int d = six[p * 2 + par].y;
                    if (d != cur) {
                        if (cur >= 0) {
                            atomicMaxF(&out[(size_t)cur * 64 + lane],      m0);
                            atomicMaxF(&out[(size_t)cur * 64 + 32 + lane], m1);
                        }
                        cur = d;
                        m0 = -3.4e38f; m1 = -3.4e38f;
                    }
                    m0 = fmaxf(m0, h0);
                    m1 = fmaxf(m1, h1);
                }
            }
        } else {
#pragma unroll
            for (int p = 0; p < 8; p++) {
                float hea, hoa, heb, hob;
                unpack2(acc[p][0], hea, hoa);
                unpack2(acc[p][1], heb, hob);
#pragma unroll
                for (int par = 0; par < 2; par++) {
                    const int e = p * 2 + par;
                    if (!((mask >> e) & 1u)) continue;
                    const float h0 = (par ? hoa : hea) + b2a;
                    const float h1 = (par ? hob : heb) + b2b;
                    const int d = six[e].y;
                    if (d != cur) {
                        if (cur >= 0) {
                            atomicMaxF(&out[(size_t)cur * 64 + lane],      m0);
                            atomicMaxF(&out[(size_t)cur * 64 + 32 + lane], m1);
                        }
                        cur = d;
                        m0 = -3.4e38f; m1 = -3.4e38f;
                    }
                    m0 = fmaxf(m0, h0);
                    m1 = fmaxf(m1, h1);
                }
            }
        }
    }
    if (cur >= 0) {
        atomicMaxF(&out[(size_t)cur * 64 + lane],      m0);
        atomicMaxF(&out[(size_t)cur * 64 + 32 + lane], m1);
    }
}

extern "C" void kernel_launch(void* const* d_in, const int* in_sizes, int n_in,
                              void* d_out, int out_size) {
    const float* x     = (const float*)d_in[0];
    const float* pos   = (const float*)d_in[1];
    const int*   batch = (const int*)d_in[2];
    const int*   ei    = (const int*)d_in[3];
    const float* W1    = (const float*)d_in[4];
    const float* b1    = (const float*)d_in[5];
    const float* W2    = (const float*)d_in[6];
    const float* b2    = (const float*)d_in[7];
    float* out = (float*)d_out;

    const long long E = (long long)in_sizes[3] / 2;

    cudaFuncSetAttribute(edge_kernel, cudaFuncAttributeMaxDynamicSharedMemorySize, 33280);

    int tail = out_size - NNODES * 64;
    if (tail < 0) tail = 0;
    node_kernel<<<296, 256>>>(x, pos, W1, b1, W2, b2, out, ei, E, batch, tail);
    edge_kernel<<<740, 128, 33280>>>(ei, E, W2, b2, out);
}

// round 16
// speedup vs baseline: 5.1816x; 1.0680x over previous
#include <cuda_runtime.h>
#include <cstdint>

#define NNODES 32768
#define EB 8     // node-kernel batch
#define ET 16    // edge-kernel tile (8 fma2-packed edge pairs, ONE gemm pass)

__device__ float2 g_u[NNODES * 32];  // [n][j] = (u_j, u_j+32) ; u = g_a + pos·W1r
__device__ float2 g_v[NNODES * 32];  // [n][j] = (v_j, v_j+32) ; v = pos·W1r
__device__ long long g_Ereal;        // boundary of the real-edge prefix

__device__ __forceinline__ void atomicMaxF(float* addr, float v) {
    if (v >= 0.0f) atomicMax((int*)addr, __float_as_int(v));
    else           atomicMin((unsigned int*)addr, __float_as_uint(v));
}
__device__ __forceinline__ unsigned long long pack2(float lo, float hi) {
    unsigned long long r;
    asm("mov.b64 %0, {%1,%2};" : "=l"(r) : "f"(lo), "f"(hi));
    return r;
}
__device__ __forceinline__ void unpack2(unsigned long long p, float& lo, float& hi) {
    asm("mov.b64 {%0,%1}, %2;" : "=f"(lo), "=f"(hi) : "l"(p));
}
__device__ __forceinline__ void fma2(unsigned long long& acc,
                                     unsigned long long a, unsigned long long b) {
    asm("fma.rn.f32x2 %0, %1, %2, %3;" : "=l"(acc) : "l"(a), "l"(b), "l"(acc));
}

// Node-kernel W2 staging (original k-pair-major order).
__device__ __forceinline__ void stage_w2_node(const float* __restrict__ W2,
                                              float4* w2a, float4* w2b, int tid, int nthr) {
    for (int idx = tid; idx < 16 * 32; idx += nthr) {
        const int q = idx >> 5, j = idx & 31;
        const float* r0 = W2 + (4 * q) * 64;
        w2a[idx] = make_float4(r0[j],      r0[64 + j],      r0[128 + j],      r0[192 + j]);
        w2b[idx] = make_float4(r0[j + 32], r0[64 + j + 32], r0[128 + j + 32], r0[192 + j + 32]);
    }
}

// Edge-kernel W2 staging in PERMUTED k-order matching the t-tile layout:
// k-position m: m=2j <-> channel j, m=2j+1 <-> channel j+32.
// Positions 4q..4q+3 <-> W2 rows (2q, 2q+32, 2q+1, 2q+33).
__device__ __forceinline__ void stage_w2_edge(const float* __restrict__ W2,
                                              float4* w2a, float4* w2b, int tid, int nthr) {
    for (int idx = tid; idx < 16 * 32; idx += nthr) {
        const int q = idx >> 5, j = idx & 31;
        w2a[idx] = make_float4(W2[(2 * q) * 64 + j],      W2[(2 * q + 32) * 64 + j],
                               W2[(2 * q + 1) * 64 + j],  W2[(2 * q + 33) * 64 + j]);
        w2b[idx] = make_float4(W2[(2 * q) * 64 + j + 32],     W2[(2 * q + 32) * 64 + j + 32],
                               W2[(2 * q + 1) * 64 + j + 32], W2[(2 * q + 33) * 64 + j + 32]);
    }
}

// ---------------------------------------------------------------------------
// Kernel 1: per-node + fused pre-work (bsearch by block 0/warp 0, tail copy).
// ---------------------------------------------------------------------------
__global__ void __launch_bounds__(256, 2) node_kernel(
    const float* __restrict__ x, const float* __restrict__ pos,
    const float* __restrict__ W1, const float* __restrict__ b1,
    const float* __restrict__ W2, const float* __restrict__ b2,
    float* __restrict__ out,
    const int* __restrict__ ei, long long E,
    const int* __restrict__ batch, int tail)
{
    __shared__ float4 w2a[16 * 32];
    __shared__ float4 w2b[16 * 32];
    __shared__ __align__(16) float tds[8][EB * 64];

    const int tid = threadIdx.x, lane = tid & 31, w = tid >> 5;

    if (blockIdx.x == 0 && w == 0) {
        long long lo = -1, hi = E;            // pred(lo)=false, pred(hi)=true
        while (hi - lo > 1) {
            const long long step = (hi - lo) / 32 + 1;
            const long long p = lo + (long long)(lane + 1) * step;
            bool pr = true;
            if (p < hi) pr = (ei[p] == ei[E + p]);
            const unsigned b = __ballot_sync(0xffffffffu, pr);
            const int k = __ffs(b) - 1;
            const long long nhi = lo + (long long)(k + 1) * step;
            lo = lo + (long long)k * step;
            hi = nhi < hi ? nhi : hi;
        }
        if (lane == 0) g_Ereal = hi;
    }

    stage_w2_node(W2, w2a, w2b, tid, 256);
    __syncthreads();
    float* td = tds[w];

    float wxa[4], wxb[4];
#pragma unroll
    for (int i = 0; i < 4; i++) { wxa[i] = W1[i * 64 + lane]; wxb[i] = W1[i * 64 + lane + 32]; }
    const float wra0 = W1[4 * 64 + lane],      wra1 = W1[5 * 64 + lane],      wra2 = W1[6 * 64 + lane];
    const float wrb0 = W1[4 * 64 + lane + 32], wrb1 = W1[5 * 64 + lane + 32], wrb2 = W1[6 * 64 + lane + 32];
    const float b1a = b1[lane], b1b = b1[lane + 32];
    const float b2a = b2[lane], b2b = b2[lane + 32];

    const int gw = blockIdx.x * 8 + w, nW = gridDim.x * 8;
    const int perWarp = (NNODES + nW - 1) / nW;
    const int n0 = gw * perWarp;
    int n1 = n0 + perWarp; if (n1 > NNODES) n1 = NNODES;

    for (int base = n0; base < n1; base += EB) {
        const int nb = min(EB, n1 - base);
        __syncwarp();
#pragma unroll
        for (int i = 0; i < EB; i++) {
            if (i >= nb) break;
            const int n = base + i;
            const float x0 = x[n * 4 + 0], x1 = x[n * 4 + 1];
            const float x2 = x[n * 4 + 2], x3 = x[n * 4 + 3];
            float t0 = fmaf(x3, wxa[3], fmaf(x2, wxa[2], fmaf(x1, wxa[1], fmaf(x0, wxa[0], b1a))));
            float t1 = fmaf(x3, wxb[3], fmaf(x2, wxb[2], fmaf(x1, wxb[1], fmaf(x0, wxb[0], b1b))));
            const float p0 = pos[n * 3 + 0], p1 = pos[n * 3 + 1], p2 = pos[n * 3 + 2];
            const float v0 = fmaf(p2, wra2, fmaf(p1, wra1, p0 * wra0));
            const float v1 = fmaf(p2, wrb2, fmaf(p1, wrb1, p0 * wrb0));
            g_v[n * 32 + lane] = make_float2(v0, v1);
            g_u[n * 32 + lane] = make_float2(t0 + v0, t1 + v1);
            td[i * 64 + lane]      = fmaxf(t0, 0.0f);
            td[i * 64 + lane + 32] = fmaxf(t1, 0.0f);
        }
        __syncwarp();

        unsigned long long acc[EB][2];
#pragma unroll
        for (int i = 0; i < EB; i++) { acc[i][0] = 0ull; acc[i][1] = 0ull; }
#pragma unroll
        for (int q = 0; q < 16; q++) {
            const ulonglong2 wa = *reinterpret_cast<const ulonglong2*>(&w2a[q * 32 + lane]);
            const ulonglong2 wb = *reinterpret_cast<const ulonglong2*>(&w2b[q * 32 + lane]);
#pragma unroll
            for (int i = 0; i < EB; i++) {
                const ulonglong2 tq = *reinterpret_cast<const ulonglong2*>(&td[i * 64 + q * 4]);
                fma2(acc[i][0], tq.x, wa.x);
                fma2(acc[i][0], tq.y, wa.y);
                fma2(acc[i][1], tq.x, wb.x);
                fma2(acc[i][1], tq.y, wb.y);
            }
        }
#pragma unroll
        for (int i = 0; i < EB; i++) {
            if (i >= nb) break;
            float a, b, c, d;
            unpack2(acc[i][0], a, b);
            unpack2(acc[i][1], c, d);
            const int n = base + i;
            out[(size_t)n * 64 + lane]      = a + b + b2a;
            out[(size_t)n * 64 + 32 + lane] = c + d + b2b;
        }
    }

    for (int i = blockIdx.x * blockDim.x + tid; i < tail; i += gridDim.x * blockDim.x) {
        float v;
        if (i < NNODES * 3) v = pos[i];
        else {
            const int k = i - NNODES * 3;
            v = (k < NNODES) ? (float)batch[k] : 0.0f;
        }
        out[NNODES * 64 + i] = v;
    }
}

// ---------------------------------------------------------------------------
// Kernel 2: per-edge over [0, g_Ereal). 16 edges/tile; t-phase by edge PAIRS
// with one conflict-free STS.128 per lane per pair; float2 u/v gathers;
// permuted-k gemm; index prefetch one tile ahead in registers.
// ---------------------------------------------------------------------------
__global__ void __launch_bounds__(128, 5) edge_kernel(
    const int* __restrict__ ei, long long E,
    const float* __restrict__ W2, const float* __restrict__ b2,
    float* __restrict__ out)
{
    extern __shared__ char smem[];
    float4* w2a  = (float4*)smem;                 //  8 KB
    float4* w2b  = (float4*)(smem + 8192);        //  8 KB
    float*  tds  = (float*)(smem + 16384);        // 16 KB: 4 warps x 8 pairs x 128
    int2*   sidx = (int2*)(smem + 32768);         // 512 B: 4 warps x 16

    const int tid = threadIdx.x, lane = tid & 31, w = tid >> 5;
    const unsigned FULL = 0xffffffffu;
    stage_w2_edge(W2, w2a, w2b, tid, 128);
    __syncthreads();

    float* tb = tds + w * 1024;
    int2*  six = sidx + w * 16;

    const float b2a = b2[lane], b2b = b2[lane + 32];
    const int* __restrict__ srcA = ei;
    const int* __restrict__ dstA = ei + E;

    const long long Er = g_Ereal;
    const long long gw = blockIdx.x * 4 + w;
    const long long nW = (long long)gridDim.x * 4;
    long long chunk = (Er + nW - 1) / nW;
    chunk = (chunk + ET - 1) / ET * ET;
    const long long e0 = gw * chunk;
    long long e1 = e0 + chunk; if (e1 > Er) e1 = Er;
    if (e0 >= e1) return;

    int cur = -1;
    float m0 = -3.4e38f, m1 = -3.4e38f;
    int dprev = -1;
    float2 vc = make_float2(0.0f, 0.0f);

    // prologue: first tile's indices into registers
    int sL = 0, dL = 0;
    if (lane < ET) {
        const long long e = e0 + lane;
        if (e < e1) { sL = srcA[e]; dL = dstA[e]; }
    }

    for (long long base = e0; base < e1; base += ET) {
        __syncwarp();   // protect six / tb reuse across iterations

        if (lane < ET) six[lane] = make_int2(sL, dL);
        const unsigned mask = __ballot_sync(FULL, (lane < ET) && (sL != dL));

        // prefetch next tile's indices NOW; they age under the gemm
        {
            const long long e = base + ET + lane;
            sL = 0; dL = 0;
            if (lane < ET && e < e1) { sL = srcA[e]; dL = dstA[e]; }
        }
        if (!mask) continue;
        __syncwarp();

        // ---- t-phase: edge pairs; t = relu(u[s] - v[d]); one STS.128/pair ----
#pragma unroll
        for (int p = 0; p < 8; p++) {
            const int4 sd = *reinterpret_cast<const int4*>(&six[2 * p]);  // (s0,d0,s1,d1)
            if (sd.y != dprev) { vc = g_v[sd.y * 32 + lane]; dprev = sd.y; }
            const float2 u0 = g_u[sd.x * 32 + lane];
            const float te0a = fmaxf(u0.x - vc.x, 0.0f);
            const float te0b = fmaxf(u0.y - vc.y, 0.0f);
            if (sd.w != dprev) { vc = g_v[sd.w * 32 + lane]; dprev = sd.w; }
            const float2 u1 = g_u[sd.z * 32 + lane];
            const float te1a = fmaxf(u1.x - vc.x, 0.0f);
            const float te1b = fmaxf(u1.y - vc.y, 0.0f);
            // float4 = (t_e0_j, t_e1_j, t_e0_j32, t_e1_j32) at k-positions 2lane, 2lane+1
            *reinterpret_cast<float4*>(tb + p * 128 + lane * 4) =
                make_float4(te0a, te1a, te0b, te1b);
        }
        __syncwarp();

        // ---- single gemm pass over 8 pairs (16 edges), permuted-k W2 ----
        unsigned long long acc[8][2];
#pragma unroll
        for (int p = 0; p < 8; p++) { acc[p][0] = 0ull; acc[p][1] = 0ull; }

#pragma unroll
        for (int q = 0; q < 16; q++) {
            const float4 wa = w2a[q * 32 + lane];
            const float4 wb = w2b[q * 32 + lane];
            const unsigned long long pa0 = pack2(wa.x, wa.x), pa1 = pack2(wa.y, wa.y);
            const unsigned long long pa2 = pack2(wa.z, wa.z), pa3 = pack2(wa.w, wa.w);
            const unsigned long long pb0 = pack2(wb.x, wb.x), pb1 = pack2(wb.y, wb.y);
            const unsigned long long pb2 = pack2(wb.z, wb.z), pb3 = pack2(wb.w, wb.w);
#pragma unroll
            for (int p = 0; p < 8; p++) {
                const float* tp = tb + p * 128 + 8 * q;
                const ulonglong2 t01 = *reinterpret_cast<const ulonglong2*>(tp);
                const ulonglong2 t23 = *reinterpret_cast<const ulonglong2*>(tp + 4);
                fma2(acc[p][0], t01.x, pa0);
                fma2(acc[p][0], t01.y, pa1);
                fma2(acc[p][0], t23.x, pa2);
                fma2(acc[p][0], t23.y, pa3);
                fma2(acc[p][1], t01.x, pb0);
                fma2(acc[p][1], t01.y, pb1);
                fma2(acc[p][1], t23.x, pb2);
                fma2(acc[p][1], t23.y, pb3);
            }
        }

        // ---- flush: running per-dst max -> atomics ----
        if (mask == 0xFFFFu) {
#pragma unroll
            for (int p = 0; p < 8; p++) {
                float hea, hoa, heb, hob;
                unpack2(acc[p][0], hea, hoa);
                unpack2(acc[p][1], heb, hob);
#pragma unroll
                for (int par = 0; par < 2; par++) {
                    const float h0 = (par ? hoa : hea) + b2a;
                    const float h1 = (par ? hob : heb) + b2b;
                    const int d = six[p * 2 + par].y;
                    if (d != cur) {
                        if (cur >= 0) {
                            atomicMaxF(&out[(size_t)cur * 64 + lane],      m0);
                            atomicMaxF(&out[(size_t)cur * 64 + 32 + lane], m1);
                        }
                        cur = d;
                        m0 = -3.4e38f; m1 = -3.4e38f;
                    }
                    m0 = fmaxf(m0, h0);
                    m1 = fmaxf(m1, h1);
                }
            }
        } else {
#pragma unroll
            for (int p = 0; p < 8; p++) {
                float hea, hoa, heb, hob;
                unpack2(acc[p][0], hea, hoa);
                unpack2(acc[p][1], heb, hob);
#pragma unroll
                for (int par = 0; par < 2; par++) {
                    const int e = p * 2 + par;
                    if (!((mask >> e) & 1u)) continue;
                    const float h0 = (par ? hoa : hea) + b2a;
                    const float h1 = (par ? hob : heb) + b2b;
                    const int d = six[e].y;
                    if (d != cur) {
                        if (cur >= 0) {
                            atomicMaxF(&out[(size_t)cur * 64 + lane],      m0);
                            atomicMaxF(&out[(size_t)cur * 64 + 32 + lane], m1);
                        }
                        cur = d;
                        m0 = -3.4e38f; m1 = -3.4e38f;
                    }
                    m0 = fmaxf(m0, h0);
                    m1 = fmaxf(m1, h1);
                }
            }
        }
    }
    if (cur >= 0) {
        atomicMaxF(&out[(size_t)cur * 64 + lane],      m0);
        atomicMaxF(&out[(size_t)cur * 64 + 32 + lane], m1);
    }
}

extern "C" void kernel_launch(void* const* d_in, const int* in_sizes, int n_in,
                              void* d_out, int out_size) {
    const float* x     = (const float*)d_in[0];
    const float* pos   = (const float*)d_in[1];
    const int*   batch = (const int*)d_in[2];
    const int*   ei    = (const int*)d_in[3];
    const float* W1    = (const float*)d_in[4];
    const float* b1    = (const float*)d_in[5];
    const float* W2    = (const float*)d_in[6];
    const float* b2    = (const float*)d_in[7];
    float* out = (float*)d_out;

    const long long E = (long long)in_sizes[3] / 2;

    cudaFuncSetAttribute(edge_kernel, cudaFuncAttributeMaxDynamicSharedMemorySize, 33280);

    int tail = out_size - NNODES * 64;
    if (tail < 0) tail = 0;
    node_kernel<<<296, 256>>>(x, pos, W1, b1, W2, b2, out, ei, E, batch, tail);
    edge_kernel<<<740, 128, 33280>>>(ei, E, W2, b2, out);
}

// round 17
// speedup vs baseline: 5.2845x; 1.0199x over previous
#include <cuda_runtime.h>
#include <cstdint>

#define NNODES 32768
#define EB 8     // node-kernel batch
#define ET 16    // edge-kernel tile (8 fma2-packed edge pairs, ONE gemm pass)

__device__ float2 g_u[NNODES * 32];  // [n][j] = (u_j, u_j+32) ; u = g_a + pos·W1r
__device__ float2 g_v[NNODES * 32];  // [n][j] = (v_j, v_j+32) ; v = pos·W1r
__device__ long long g_Ereal;        // boundary of the real-edge prefix

__device__ __forceinline__ void atomicMaxF(float* addr, float v) {
    if (v >= 0.0f) atomicMax((int*)addr, __float_as_int(v));
    else           atomicMin((unsigned int*)addr, __float_as_uint(v));
}
__device__ __forceinline__ unsigned long long pack2(float lo, float hi) {
    unsigned long long r;
    asm("mov.b64 %0, {%1,%2};" : "=l"(r) : "f"(lo), "f"(hi));
    return r;
}
__device__ __forceinline__ void unpack2(unsigned long long p, float& lo, float& hi) {
    asm("mov.b64 {%0,%1}, %2;" : "=f"(lo), "=f"(hi) : "l"(p));
}
__device__ __forceinline__ void fma2(unsigned long long& acc,
                                     unsigned long long a, unsigned long long b) {
    asm("fma.rn.f32x2 %0, %1, %2, %3;" : "=l"(acc) : "l"(a), "l"(b), "l"(acc));
}

// Node-kernel W2 staging (original k-pair-major order).
__device__ __forceinline__ void stage_w2_node(const float* __restrict__ W2,
                                              float4* w2a, float4* w2b, int tid, int nthr) {
    for (int idx = tid; idx < 16 * 32; idx += nthr) {
        const int q = idx >> 5, j = idx & 31;
        const float* r0 = W2 + (4 * q) * 64;
        w2a[idx] = make_float4(r0[j],      r0[64 + j],      r0[128 + j],      r0[192 + j]);
        w2b[idx] = make_float4(r0[j + 32], r0[64 + j + 32], r0[128 + j + 32], r0[192 + j + 32]);
    }
}

// Edge-kernel W2 staging in PERMUTED k-order matching the t-tile layout:
// k-position m: m=2j <-> channel j, m=2j+1 <-> channel j+32.
// Positions 4q..4q+3 <-> W2 rows (2q, 2q+32, 2q+1, 2q+33).
__device__ __forceinline__ void stage_w2_edge(const float* __restrict__ W2,
                                              float4* w2a, float4* w2b, int tid, int nthr) {
    for (int idx = tid; idx < 16 * 32; idx += nthr) {
        const int q = idx >> 5, j = idx & 31;
        w2a[idx] = make_float4(W2[(2 * q) * 64 + j],      W2[(2 * q + 32) * 64 + j],
                               W2[(2 * q + 1) * 64 + j],  W2[(2 * q + 33) * 64 + j]);
        w2b[idx] = make_float4(W2[(2 * q) * 64 + j + 32],     W2[(2 * q + 32) * 64 + j + 32],
                               W2[(2 * q + 1) * 64 + j + 32], W2[(2 * q + 33) * 64 + j + 32]);
    }
}

// ---------------------------------------------------------------------------
// Kernel 1: per-node + fused pre-work (bsearch by block 0/warp 0, tail copy).
// ---------------------------------------------------------------------------
__global__ void __launch_bounds__(256, 2) node_kernel(
    const float* __restrict__ x, const float* __restrict__ pos,
    const float* __restrict__ W1, const float* __restrict__ b1,
    const float* __restrict__ W2, const float* __restrict__ b2,
    float* __restrict__ out,
    const int* __restrict__ ei, long long E,
    const int* __restrict__ batch, int tail)
{
    __shared__ float4 w2a[16 * 32];
    __shared__ float4 w2b[16 * 32];
    __shared__ __align__(16) float tds[8][EB * 64];

    const int tid = threadIdx.x, lane = tid & 31, w = tid >> 5;

    if (blockIdx.x == 0 && w == 0) {
        long long lo = -1, hi = E;            // pred(lo)=false, pred(hi)=true
        while (hi - lo > 1) {
            const long long step = (hi - lo) / 32 + 1;
            const long long p = lo + (long long)(lane + 1) * step;
            bool pr = true;
            if (p < hi) pr = (ei[p] == ei[E + p]);
            const unsigned b = __ballot_sync(0xffffffffu, pr);
            const int k = __ffs(b) - 1;
            const long long nhi = lo + (long long)(k + 1) * step;
            lo = lo + (long long)k * step;
            hi = nhi < hi ? nhi : hi;
        }
        if (lane == 0) g_Ereal = hi;
    }

    stage_w2_node(W2, w2a, w2b, tid, 256);
    __syncthreads();
    float* td = tds[w];

    float wxa[4], wxb[4];
#pragma unroll
    for (int i = 0; i < 4; i++) { wxa[i] = W1[i * 64 + lane]; wxb[i] = W1[i * 64 + lane + 32]; }
    const float wra0 = W1[4 * 64 + lane],      wra1 = W1[5 * 64 + lane],      wra2 = W1[6 * 64 + lane];
    const float wrb0 = W1[4 * 64 + lane + 32], wrb1 = W1[5 * 64 + lane + 32], wrb2 = W1[6 * 64 + lane + 32];
    const float b1a = b1[lane], b1b = b1[lane + 32];
    const float b2a = b2[lane], b2b = b2[lane + 32];

    const int gw = blockIdx.x * 8 + w, nW = gridDim.x * 8;
    const int perWarp = (NNODES + nW - 1) / nW;
    const int n0 = gw * perWarp;
    int n1 = n0 + perWarp; if (n1 > NNODES) n1 = NNODES;

    for (int base = n0; base < n1; base += EB) {
        const int nb = min(EB, n1 - base);
        __syncwarp();
#pragma unroll
        for (int i = 0; i < EB; i++) {
            if (i >= nb) break;
            const int n = base + i;
            const float x0 = x[n * 4 + 0], x1 = x[n * 4 + 1];
            const float x2 = x[n * 4 + 2], x3 = x[n * 4 + 3];
            float t0 = fmaf(x3, wxa[3], fmaf(x2, wxa[2], fmaf(x1, wxa[1], fmaf(x0, wxa[0], b1a))));
            float t1 = fmaf(x3, wxb[3], fmaf(x2, wxb[2], fmaf(x1, wxb[1], fmaf(x0, wxb[0], b1b))));
            const float p0 = pos[n * 3 + 0], p1 = pos[n * 3 + 1], p2 = pos[n * 3 + 2];
            const float v0 = fmaf(p2, wra2, fmaf(p1, wra1, p0 * wra0));
            const float v1 = fmaf(p2, wrb2, fmaf(p1, wrb1, p0 * wrb0));
            g_v[n * 32 + lane] = make_float2(v0, v1);
            g_u[n * 32 + lane] = make_float2(t0 + v0, t1 + v1);
            td[i * 64 + lane]      = fmaxf(t0, 0.0f);
            td[i * 64 + lane + 32] = fmaxf(t1, 0.0f);
        }
        __syncwarp();

        unsigned long long acc[EB][2];
#pragma unroll
        for (int i = 0; i < EB; i++) { acc[i][0] = 0ull; acc[i][1] = 0ull; }
#pragma unroll
        for (int q = 0; q < 16; q++) {
            const ulonglong2 wa = *reinterpret_cast<const ulonglong2*>(&w2a[q * 32 + lane]);
            const ulonglong2 wb = *reinterpret_cast<const ulonglong2*>(&w2b[q * 32 + lane]);
#pragma unroll
            for (int i = 0; i < EB; i++) {
                const ulonglong2 tq = *reinterpret_cast<const ulonglong2*>(&td[i * 64 + q * 4]);
                fma2(acc[i][0], tq.x, wa.x);
                fma2(acc[i][0], tq.y, wa.y);
                fma2(acc[i][1], tq.x, wb.x);
                fma2(acc[i][1], tq.y, wb.y);
            }
        }
#pragma unroll
        for (int i = 0; i < EB; i++) {
            if (i >= nb) break;
            float a, b, c, d;
            unpack2(acc[i][0], a, b);
            unpack2(acc[i][1], c, d);
            const int n = base + i;
            out[(size_t)n * 64 + lane]      = a + b + b2a;
            out[(size_t)n * 64 + 32 + lane] = c + d + b2b;
        }
    }

    for (int i = blockIdx.x * blockDim.x + tid; i < tail; i += gridDim.x * blockDim.x) {
        float v;
        if (i < NNODES * 3) v = pos[i];
        else {
            const int k = i - NNODES * 3;
            v = (k < NNODES) ? (float)batch[k] : 0.0f;
        }
        out[NNODES * 64 + i] = v;
    }
}

// ---------------------------------------------------------------------------
// Kernel 2: per-edge over [0, g_Ereal). 16 edges/tile; pairwise t-phase with
// conflict-free STS.128; float2 u/v gathers; permuted-k gemm; index prefetch.
// ---------------------------------------------------------------------------
__global__ void __launch_bounds__(128, 5) edge_kernel(
    const int* __restrict__ ei, long long E,
    const float* __restrict__ W2, const float* __restrict__ b2,
    float* __restrict__ out)
{
    extern __shared__ char smem[];
    float4* w2a  = (float4*)smem;                 //  8 KB
    float4* w2b  = (float4*)(smem + 8192);        //  8 KB
    float*  tds  = (float*)(smem + 16384);        // 16 KB: 4 warps x 8 pairs x 128
    int2*   sidx = (int2*)(smem + 32768);         // 512 B: 4 warps x 16

    const int tid = threadIdx.x, lane = tid & 31, w = tid >> 5;
    const unsigned FULL = 0xffffffffu;
    stage_w2_edge(W2, w2a, w2b, tid, 128);
    __syncthreads();

    float* tb = tds + w * 1024;
    int2*  six = sidx + w * 16;

    const float b2a = b2[lane], b2b = b2[lane + 32];
    const int* __restrict__ srcA = ei;
    const int* __restrict__ dstA = ei + E;

    const long long Er = g_Ereal;
    const long long gw = blockIdx.x * 4 + w;
    const long long nW = (long long)gridDim.x * 4;
    long long chunk = (Er + nW - 1) / nW;
    chunk = (chunk + ET - 1) / ET * ET;
    const long long e0 = gw * chunk;
    long long e1 = e0 + chunk; if (e1 > Er) e1 = Er;
    if (e0 >= e1) return;

    int cur = -1;
    float m0 = -3.4e38f, m1 = -3.4e38f;
    int dprev = -1;
    float2 vc = make_float2(0.0f, 0.0f);

    // prologue: first tile's indices into registers
    int sL = 0, dL = 0;
    if (lane < ET) {
        const long long e = e0 + lane;
        if (e < e1) { sL = srcA[e]; dL = dstA[e]; }
    }

    for (long long base = e0; base < e1; base += ET) {
        __syncwarp();   // protect six / tb reuse across iterations

        if (lane < ET) six[lane] = make_int2(sL, dL);
        const unsigned mask = __ballot_sync(FULL, (lane < ET) && (sL != dL));

        // prefetch next tile's indices NOW; they age under the gemm
        {
            const long long e = base + ET + lane;
            sL = 0; dL = 0;
            if (lane < ET && e < e1) { sL = srcA[e]; dL = dstA[e]; }
        }
        if (!mask) continue;
        __syncwarp();

        // ---- t-phase: edge pairs; t = relu(u[s] - v[d]); one STS.128/pair ----
#pragma unroll
        for (int p = 0; p < 8; p++) {
            const int4 sd = *reinterpret_cast<const int4*>(&six[2 * p]);  // (s0,d0,s1,d1)
            if (sd.y != dprev) { vc = g_v[sd.y * 32 + lane]; dprev = sd.y; }
            const float2 u0 = g_u[sd.x * 32 + lane];
            const float te0a = fmaxf(u0.x - vc.x, 0.0f);
            const float te0b = fmaxf(u0.y - vc.y, 0.0f);
            if (sd.w != dprev) { vc = g_v[sd.w * 32 + lane]; dprev = sd.w; }
            const float2 u1 = g_u[sd.z * 32 + lane];
            const float te1a = fmaxf(u1.x - vc.x, 0.0f);
            const float te1b = fmaxf(u1.y - vc.y, 0.0f);
            *reinterpret_cast<float4*>(tb + p * 128 + lane * 4) =
                make_float4(te0a, te1a, te0b, te1b);
        }
        __syncwarp();

        // ---- single gemm pass over 8 pairs (16 edges), permuted-k W2 ----
        unsigned long long acc[8][2];
#pragma unroll
        for (int p = 0; p < 8; p++) { acc[p][0] = 0ull; acc[p][1] = 0ull; }

#pragma unroll
        for (int q = 0; q < 16; q++) {
            const float4 wa = w2a[q * 32 + lane];
            const float4 wb = w2b[q * 32 + lane];
            const unsigned long long pa0 = pack2(wa.x, wa.x), pa1 = pack2(wa.y, wa.y);
            const unsigned long long pa2 = pack2(wa.z, wa.z), pa3 = pack2(wa.w, wa.w);
            const unsigned long long pb0 = pack2(wb.x, wb.x), pb1 = pack2(wb.y, wb.y);
            const unsigned long long pb2 = pack2(wb.z, wb.z), pb3 = pack2(wb.w, wb.w);
#pragma unroll
            for (int p = 0; p < 8; p++) {
                const float* tp = tb + p * 128 + 8 * q;
                const ulonglong2 t01 = *reinterpret_cast<const ulonglong2*>(tp);
                const ulonglong2 t23 = *reinterpret_cast<const ulonglong2*>(tp + 4);
                fma2(acc[p][0], t01.x, pa0);
                fma2(acc[p][0], t01.y, pa1);
                fma2(acc[p][0], t23.x, pa2);
                fma2(acc[p][0], t23.y, pa3);
                fma2(acc[p][1], t01.x, pb0);
                fma2(acc[p][1], t01.y, pb1);
                fma2(acc[p][1], t23.x, pb2);
                fma2(acc[p][1], t23.y, pb3);
            }
        }

        // ---- flush: running per-dst max -> atomics ----
        if (mask == 0xFFFFu) {
#pragma unroll
            for (int p = 0; p < 8; p++) {
                float hea, hoa, heb, hob;
                unpack2(acc[p][0], hea, hoa);
                unpack2(acc[p][1], heb, hob);
#pragma unroll
                for (int par = 0; par < 2; par++) {
                    const float h0 = (par ? hoa : hea) + b2a;
                    const float h1 = (par ? hob : heb) + b2b;
                    const int d = six[p * 2 + par].y;
                    if (d != cur) {
                        if (cur >= 0) {
                            atomicMaxF(&out[(size_t)cur * 64 + lane],      m0);
                            atomicMaxF(&out[(size_t)cur * 64 + 32 + lane], m1);
                        }
                        cur = d;
                        m0 = -3.4e38f; m1 = -3.4e38f;
                    }
                    m0 = fmaxf(m0, h0);
                    m1 = fmaxf(m1, h1);
                }
            }
        } else {
#pragma unroll
            for (int p = 0; p < 8; p++) {
                float hea, hoa, heb, hob;
                unpack2(acc[p][0], hea, hoa);
                unpack2(acc[p][1], heb, hob);
#pragma unroll
                for (int par = 0; par < 2; par++) {
                    const int e = p * 2 + par;
                    if (!((mask >> e) & 1u)) continue;
                    const float h0 = (par ? hoa : hea) + b2a;
                    const float h1 = (par ? hob : heb) + b2b;
                    const int d = six[e].y;
                    if (d != cur) {
                        if (cur >= 0) {
                            atomicMaxF(&out[(size_t)cur * 64 + lane],      m0);
                            atomicMaxF(&out[(size_t)cur * 64 + 32 + lane], m1);
                        }
                        cur = d;
                        m0 = -3.4e38f; m1 = -3.4e38f;
                    }
                    m0 = fmaxf(m0, h0);
                    m1 = fmaxf(m1, h1);
                }
            }
        }
    }
    if (cur >= 0) {
        atomicMaxF(&out[(size_t)cur * 64 + lane],      m0);
        atomicMaxF(&out[(size_t)cur * 64 + 32 + lane], m1);
    }
}

extern "C" void kernel_launch(void* const* d_in, const int* in_sizes, int n_in,
                              void* d_out, int out_size) {
    const float* x     = (const float*)d_in[0];
    const float* pos   = (const float*)d_in[1];
    const int*   batch = (const int*)d_in[2];
    const int*   ei    = (const int*)d_in[3];
    const float* W1    = (const float*)d_in[4];
    const float* b1    = (const float*)d_in[5];
    const float* W2    = (const float*)d_in[6];
    const float* b2    = (const float*)d_in[7];
    float* out = (float*)d_out;

    const long long E = (long long)in_sizes[3] / 2;

    static int attrs_set = 0;
    if (!attrs_set) {
        cudaFuncSetAttribute(edge_kernel, cudaFuncAttributeMaxDynamicSharedMemorySize, 33280);
        // Request max shared carveout so 5 blocks x 33280 B fit per SM
        // (default carveout caps concurrent smem and limits us to 4 blocks).
        cudaFuncSetAttribute(edge_kernel, cudaFuncAttributePreferredSharedMemoryCarveout,
                             cudaSharedmemCarveoutMaxShared);
        cudaFuncSetAttribute(node_kernel, cudaFuncAttributePreferredSharedMemoryCarveout,
                             cudaSharedmemCarveoutMaxShared);
        attrs_set = 1;
    }

    int tail = out_size - NNODES * 64;
    if (tail < 0) tail = 0;
    node_kernel<<<296, 256>>>(x, pos, W1, b1, W2, b2, out, ei, E, batch, tail);
    edge_kernel<<<740, 128, 33280>>>(ei, E, W2, b2, out);
}